// round 9
// baseline (speedup 1.0000x reference)
#include <cuda_runtime.h>
#include <cuda_bf16.h>
#include <math.h>

// Problem constants
#define Bc   2
#define Qn   4096
#define Kn   4096
#define DQ   512
#define NH   8
#define DH   32
#define INNER (NH*DH)   // 256

// ---------------- scratch (no allocs allowed) ----------------
__device__ float g_qs[Bc*Qn*INNER];   // projected, scaled q  [B,Q,256]
__device__ float g_ks[Bc*Kn*INNER];   // projected k          [B,K,256]
__device__ float g_vs[Bc*Kn*INNER];   // projected v          [B,K,256]
__device__ float g_qo[Bc*Qn*INNER];   // attention out (pre Wo) [B,Q,256]
__device__ float g_qn[Bc*NH*Qn];      // ||q_row|| per (b,h,q)  -> shift c
__device__ float g_l[Bc*NH*Qn];       // row sum-exp (vs shift c)
__device__ float g_knm[Bc*NH];        // max_k ||k_row|| per (b,h)

// ---------------- packed f32x2 helpers (sm_100+) ----------------
typedef unsigned long long ull;

__device__ __forceinline__ ull pack2(float x, float y) {
    ull r;
    asm("mov.b64 %0, {%1, %2};" : "=l"(r) : "f"(x), "f"(y));
    return r;
}
__device__ __forceinline__ void unpack2(ull v, float &x, float &y) {
    asm("mov.b64 {%0, %1}, %2;" : "=f"(x), "=f"(y) : "l"(v));
}
__device__ __forceinline__ void ffma2(ull &d, ull a, ull b) {
    asm("fma.rn.f32x2 %0, %1, %2, %0;" : "+l"(d) : "l"(a), "l"(b));
}
__device__ __forceinline__ void fadd2(ull &d, ull a) {
    asm("add.rn.f32x2 %0, %0, %1;" : "+l"(d) : "l"(a));
}

// ---------------- generic fp32 SGEMM: C = scale*(A@B) + bias ----------------
__global__ void sgemm_kernel(const float* __restrict__ A, const float* __restrict__ B,
                             const float* __restrict__ bias, float* __restrict__ C,
                             int M, int N, int K, float scale) {
    __shared__ float As[16][68];
    __shared__ float Bs[16][64];
    int tid = threadIdx.x;
    int tx = tid & 15, ty = tid >> 4;
    int bm = blockIdx.x * 64, bn = blockIdx.y * 64;

    float acc[4][4];
#pragma unroll
    for (int i = 0; i < 4; i++)
#pragma unroll
        for (int j = 0; j < 4; j++) acc[i][j] = 0.f;

    for (int k0 = 0; k0 < K; k0 += 16) {
        {
            int m = tid >> 2, kq = (tid & 3) << 2;
            float4 a = *(const float4*)&A[(size_t)(bm + m) * K + k0 + kq];
            As[kq + 0][m] = a.x; As[kq + 1][m] = a.y;
            As[kq + 2][m] = a.z; As[kq + 3][m] = a.w;
        }
        {
            int kk = tid >> 4, nq = (tid & 15) << 2;
            *(float4*)&Bs[kk][nq] = *(const float4*)&B[(size_t)(k0 + kk) * N + bn + nq];
        }
        __syncthreads();
#pragma unroll
        for (int kk = 0; kk < 16; kk++) {
            float4 a4 = *(const float4*)&As[kk][ty * 4];
            float4 b4 = *(const float4*)&Bs[kk][tx * 4];
            float av[4] = {a4.x, a4.y, a4.z, a4.w};
            float bv[4] = {b4.x, b4.y, b4.z, b4.w};
#pragma unroll
            for (int i = 0; i < 4; i++)
#pragma unroll
                for (int j = 0; j < 4; j++) acc[i][j] += av[i] * bv[j];
        }
        __syncthreads();
    }
#pragma unroll
    for (int i = 0; i < 4; i++) {
        int row = bm + ty * 4 + i;
        int col = bn + tx * 4;
        float4 o;
        o.x = acc[i][0] * scale; o.y = acc[i][1] * scale;
        o.z = acc[i][2] * scale; o.w = acc[i][3] * scale;
        if (bias) {
            o.x += bias[col + 0]; o.y += bias[col + 1];
            o.z += bias[col + 2]; o.w += bias[col + 3];
        }
        *(float4*)&C[(size_t)row * N + col] = o;
    }
}

// ---------------- norm kernels (softmax shift bound) ----------------
// qn[b,h,q] = || q_scaled(b,q,h,:) ||_2
__global__ void qnorm_kernel(const float* __restrict__ q, float* __restrict__ qn) {
    int t = blockIdx.x * 256 + threadIdx.x;          // 65536
    int h = t & 7, bq = t >> 3;
    int b = bq >> 12, qq = bq & 4095;
    const float* p = q + (size_t)bq * INNER + h * DH;
    float s = 0.f;
#pragma unroll
    for (int i = 0; i < 8; i++) {
        float4 v = *(const float4*)(p + i * 4);
        s += v.x * v.x + v.y * v.y + v.z * v.z + v.w * v.w;
    }
    qn[((b * NH + h) * Qn) + qq] = sqrtf(s);
}

// knm[b,h] = max over k of || k(b,k,h,:) ||_2
__global__ void knorm_kernel(const float* __restrict__ k, float* __restrict__ knm) {
    int bh = blockIdx.x;                 // 16 blocks
    int b = bh >> 3, h = bh & 7;
    float mx = 0.f;
    for (int row = threadIdx.x; row < Kn; row += 256) {
        const float* p = k + ((size_t)(b * Kn) + row) * INNER + h * DH;
        float s = 0.f;
#pragma unroll
        for (int i = 0; i < 8; i++) {
            float4 v = *(const float4*)(p + i * 4);
            s += v.x * v.x + v.y * v.y + v.z * v.z + v.w * v.w;
        }
        mx = fmaxf(mx, s);
    }
    __shared__ float red[256];
    red[threadIdx.x] = mx;
    __syncthreads();
    for (int s = 128; s; s >>= 1) {
        if (threadIdx.x < s) red[threadIdx.x] = fmaxf(red[threadIdx.x], red[threadIdx.x + s]);
        __syncthreads();
    }
    if (threadIdx.x == 0) knm[bh] = sqrtf(red[0]);
}

// ---------------- flash kernel: l + PV only (fixed shift c, no max) ----------
// grid = (Qn/128, NH, Bc), 256 threads, 2 CTAs/SM.
#define OFF_Q 0            // qsm[32][128]  (kd-major, transposed)
#define OFF_K 4096         // ksm[32][128]
#define OFF_V 8192         // vsm[128][32]
#define OFF_P 12288        // pt [128][128] (kk-major, row-quads XOR-swizzled)
#define OFF_L 28672        // l[128]
#define SMEM_FLOATS 28800
#define SMEM_BYTES (SMEM_FLOATS*4)   // 115200 B

__global__ void __launch_bounds__(256, 2)
flash_kernel(const float* __restrict__ qs, const float* __restrict__ ks,
             const float* __restrict__ vs, const float* __restrict__ qn,
             const float* __restrict__ knm, float* __restrict__ qo,
             float* __restrict__ lg) {
    extern __shared__ float sm[];
    float* qsm = sm + OFF_Q;
    float* ksm = sm + OFF_K;
    float* vsm = sm + OFF_V;
    float* pt  = sm + OFF_P;
    float* lsm = sm + OFF_L;

    const int b = blockIdx.z, h = blockIdx.y, q0 = blockIdx.x * 128;
    const int tid = threadIdx.x;
    const int ty = tid >> 4, tx = tid & 15;
    const int tt = tid & 127, half = tid >> 7;
    const int rgrp = tt >> 3, dgrp = tt & 7;
    const size_t bh = (size_t)(b * NH + h);

    // ---- load Q tile transposed: qsm[kd][row] ----
    {
        int row = tid >> 1, hf = tid & 1;
        const float* gq = qs + ((size_t)(b * Qn) + q0 + row) * INNER + h * DH + hf * 16;
#pragma unroll
        for (int i = 0; i < 4; i++) {
            float4 v = *(const float4*)(gq + i * 4);
            int kd = hf * 16 + i * 4;
            qsm[(kd + 0) * 128 + row] = v.x;
            qsm[(kd + 1) * 128 + row] = v.y;
            qsm[(kd + 2) * 128 + row] = v.z;
            qsm[(kd + 3) * 128 + row] = v.w;
        }
    }

    // per-row shift c and l accumulators
    float creg[8], lrow[8];
    {
        float knmv = knm[bh];
#pragma unroll
        for (int i = 0; i < 8; i++) {
            creg[i] = qn[bh * Qn + q0 + ty * 8 + i] * knmv;
            lrow[i] = 0.f;
        }
    }

    ull oacc[4][4];
#pragma unroll
    for (int ip = 0; ip < 4; ip++)
#pragma unroll
        for (int j = 0; j < 4; j++) oacc[ip][j] = 0ull;

    for (int c0 = 0; c0 < Kn; c0 += 128) {
        __syncthreads();   // prev PV done; safe to overwrite ksm/vsm/pt

        // ---- load K chunk transposed ----
        {
            int col = tid >> 1, hf = tid & 1;
            const float* gk = ks + ((size_t)(b * Kn) + c0 + col) * INNER + h * DH + hf * 16;
#pragma unroll
            for (int i = 0; i < 4; i++) {
                float4 v = *(const float4*)(gk + i * 4);
                int kd = hf * 16 + i * 4;
                ksm[(kd + 0) * 128 + col] = v.x;
                ksm[(kd + 1) * 128 + col] = v.y;
                ksm[(kd + 2) * 128 + col] = v.z;
                ksm[(kd + 3) * 128 + col] = v.w;
            }
        }
        // ---- load V chunk ----
        {
#pragma unroll
            for (int i = 0; i < 4; i++) {
                int f = tid + i * 256;
                int kk = f >> 3, d4 = (f & 7) << 2;
                *(float4*)&vsm[kk * 32 + d4] =
                    *(const float4*)(vs + ((size_t)(b * Kn) + c0 + kk) * INNER + h * DH + d4);
            }
        }
        __syncthreads();

        // ---- score GEMM in two 4-row passes; p = exp(s-c) ----
#pragma unroll
        for (int rp = 0; rp < 2; rp++) {
            const int r0 = ty * 8 + rp * 4;

            ull acc[4][4];
#pragma unroll
            for (int i = 0; i < 4; i++)
#pragma unroll
                for (int jp = 0; jp < 4; jp++) acc[i][jp] = 0ull;

#pragma unroll 4
            for (int kd = 0; kd < 32; kd++) {
                float4 a4 = *(const float4*)&qsm[kd * 128 + r0];
                ull aa[4] = {pack2(a4.x, a4.x), pack2(a4.y, a4.y),
                             pack2(a4.z, a4.z), pack2(a4.w, a4.w)};
                const ulonglong2* bp = (const ulonglong2*)&ksm[kd * 128 + tx * 8];
                ulonglong2 b01 = bp[0], b23 = bp[1];
                ull bb[4] = {b01.x, b01.y, b23.x, b23.y};
#pragma unroll
                for (int i = 0; i < 4; i++)
#pragma unroll
                    for (int jp = 0; jp < 4; jp++) ffma2(acc[i][jp], aa[i], bb[jp]);
            }

            float sc[4][8];
#pragma unroll
            for (int i = 0; i < 4; i++)
#pragma unroll
                for (int jp = 0; jp < 4; jp++)
                    unpack2(acc[i][jp], sc[i][2 * jp], sc[i][2 * jp + 1]);

            // p = exp(s - c), accumulate l locally (no cross-lane work here)
#pragma unroll
            for (int i = 0; i < 4; i++) {
                const int ri = rp * 4 + i;
                float ls = 0.f;
#pragma unroll
                for (int j = 0; j < 8; j++) {
                    float p = __expf(sc[i][j] - creg[ri]);
                    sc[i][j] = p;
                    ls += p;
                }
                lrow[ri] += ls;
            }

            // store P to pt[kk][row-quad], XOR-swizzled
            {
                const int quad = ty * 2 + rp;
#pragma unroll
                for (int j = 0; j < 8; j++) {
                    int kk = tx * 8 + j;
                    int sw = tx & 7;
                    *(float4*)&pt[kk * 128 + ((quad ^ sw) << 2)] =
                        make_float4(sc[0][j], sc[1][j], sc[2][j], sc[3][j]);
                }
            }
        }
        __syncthreads();

        // ---- PV accumulate over this half's kk range (no rescale) ----
        {
            int kb = half * 64;
#pragma unroll 2
            for (int k2 = 0; k2 < 64; k2++) {
                int kk = kb + k2;
                int sw = (kk >> 3) & 7;
                const ulonglong2* pp = (const ulonglong2*)&pt[kk * 128];
                ulonglong2 pa = pp[(rgrp * 2) ^ sw];
                ulonglong2 pb = pp[(rgrp * 2 + 1) ^ sw];
                ull p2[4] = {pa.x, pa.y, pb.x, pb.y};
                float4 v4 = *(const float4*)&vsm[kk * 32 + dgrp * 4];
                ull vv[4] = {pack2(v4.x, v4.x), pack2(v4.y, v4.y),
                             pack2(v4.z, v4.z), pack2(v4.w, v4.w)};
#pragma unroll
                for (int ip = 0; ip < 4; ip++)
#pragma unroll
                    for (int j = 0; j < 4; j++) ffma2(oacc[ip][j], p2[ip], vv[j]);
            }
        }
    }

    // ---- finalize: reduce l over tx lanes, combine halves, write O ----
#pragma unroll
    for (int i = 0; i < 8; i++) {
        float v = lrow[i];
#pragma unroll
        for (int off = 8; off; off >>= 1)
            v += __shfl_xor_sync(0xffffffffu, v, off);
        if (tx == 0) {
            lsm[ty * 8 + i] = v;
            lg[bh * Qn + q0 + ty * 8 + i] = v;
        }
    }
    __syncthreads();
    ull* red = (ull*)pt;
    if (half == 1) {
#pragma unroll
        for (int ip = 0; ip < 4; ip++)
#pragma unroll
            for (int j = 0; j < 4; j++) red[tt * 16 + ip * 4 + j] = oacc[ip][j];
    }
    __syncthreads();
    if (half == 0) {
#pragma unroll
        for (int ip = 0; ip < 4; ip++)
#pragma unroll
            for (int j = 0; j < 4; j++) fadd2(oacc[ip][j], red[tt * 16 + ip * 4 + j]);
#pragma unroll
        for (int ip = 0; ip < 4; ip++) {
            float f0[4], f1[4];
#pragma unroll
            for (int j = 0; j < 4; j++) unpack2(oacc[ip][j], f0[j], f1[j]);
            int r0 = rgrp * 8 + ip * 2;
            float inv0 = 1.0f / lsm[r0];
            float inv1 = 1.0f / lsm[r0 + 1];
            *(float4*)&qo[((size_t)(b * Qn) + q0 + r0) * INNER + h * DH + dgrp * 4] =
                make_float4(f0[0] * inv0, f0[1] * inv0, f0[2] * inv0, f0[3] * inv0);
            *(float4*)&qo[((size_t)(b * Qn) + q0 + r0 + 1) * INNER + h * DH + dgrp * 4] =
                make_float4(f1[0] * inv1, f1[1] * inv1, f1[2] * inv1, f1[3] * inv1);
        }
    }
}

// ---------------- weights kernel: w = exp(s - c) / l, written once ----------
__global__ void __launch_bounds__(256, 4)
weights_kernel(const float* __restrict__ qs, const float* __restrict__ ks,
               const float* __restrict__ qn, const float* __restrict__ knm,
               const float* __restrict__ lg, float* __restrict__ w) {
    __shared__ float qsm[32 * 128];
    __shared__ float ksm[32 * 128];

    const int b = blockIdx.z, h = blockIdx.y, q0 = blockIdx.x * 128;
    const int tid = threadIdx.x;
    const int ty = tid >> 4, tx = tid & 15;
    const size_t bh = (size_t)(b * NH + h);

    // load Q tile transposed (identical layout/order to flash_kernel)
    {
        int row = tid >> 1, hf = tid & 1;
        const float* gq = qs + ((size_t)(b * Qn) + q0 + row) * INNER + h * DH + hf * 16;
#pragma unroll
        for (int i = 0; i < 4; i++) {
            float4 v = *(const float4*)(gq + i * 4);
            int kd = hf * 16 + i * 4;
            qsm[(kd + 0) * 128 + row] = v.x;
            qsm[(kd + 1) * 128 + row] = v.y;
            qsm[(kd + 2) * 128 + row] = v.z;
            qsm[(kd + 3) * 128 + row] = v.w;
        }
    }

    float creg[8], invl[8];
    {
        float knmv = knm[bh];
#pragma unroll
        for (int i = 0; i < 8; i++) {
            size_t gi = bh * Qn + q0 + ty * 8 + i;
            creg[i] = qn[gi] * knmv;
            invl[i] = 1.0f / lg[gi];
        }
    }

    for (int c0 = 0; c0 < Kn; c0 += 128) {
        __syncthreads();   // prev chunk's reads done
        {
            int col = tid >> 1, hf = tid & 1;
            const float* gk = ks + ((size_t)(b * Kn) + c0 + col) * INNER + h * DH + hf * 16;
#pragma unroll
            for (int i = 0; i < 4; i++) {
                float4 v = *(const float4*)(gk + i * 4);
                int kd = hf * 16 + i * 4;
                ksm[(kd + 0) * 128 + col] = v.x;
                ksm[(kd + 1) * 128 + col] = v.y;
                ksm[(kd + 2) * 128 + col] = v.z;
                ksm[(kd + 3) * 128 + col] = v.w;
            }
        }
        __syncthreads();

#pragma unroll
        for (int rp = 0; rp < 2; rp++) {
            const int r0 = ty * 8 + rp * 4;

            ull acc[4][4];
#pragma unroll
            for (int i = 0; i < 4; i++)
#pragma unroll
                for (int jp = 0; jp < 4; jp++) acc[i][jp] = 0ull;

#pragma unroll 4
            for (int kd = 0; kd < 32; kd++) {
                float4 a4 = *(const float4*)&qsm[kd * 128 + r0];
                ull aa[4] = {pack2(a4.x, a4.x), pack2(a4.y, a4.y),
                             pack2(a4.z, a4.z), pack2(a4.w, a4.w)};
                const ulonglong2* bp = (const ulonglong2*)&ksm[kd * 128 + tx * 8];
                ulonglong2 b01 = bp[0], b23 = bp[1];
                ull bb[4] = {b01.x, b01.y, b23.x, b23.y};
#pragma unroll
                for (int i = 0; i < 4; i++)
#pragma unroll
                    for (int jp = 0; jp < 4; jp++) ffma2(acc[i][jp], aa[i], bb[jp]);
            }

            float sc[4][8];
#pragma unroll
            for (int i = 0; i < 4; i++)
#pragma unroll
                for (int jp = 0; jp < 4; jp++)
                    unpack2(acc[i][jp], sc[i][2 * jp], sc[i][2 * jp + 1]);

            size_t wbase = (bh * Qn + q0 + r0) * (size_t)Kn + c0 + tx * 8;
#pragma unroll
            for (int i = 0; i < 4; i++) {
                const int ri = rp * 4 + i;
                float c = creg[ri], il = invl[ri];
#pragma unroll
                for (int j = 0; j < 8; j++) sc[i][j] = __expf(sc[i][j] - c) * il;
                *(float4*)&w[wbase + (size_t)i * Kn] =
                    make_float4(sc[i][0], sc[i][1], sc[i][2], sc[i][3]);
                *(float4*)&w[wbase + (size_t)i * Kn + 4] =
                    make_float4(sc[i][4], sc[i][5], sc[i][6], sc[i][7]);
            }
        }
    }
}

// ---------------- launch ----------------
extern "C" void kernel_launch(void* const* d_in, const int* in_sizes, int n_in,
                              void* d_out, int out_size) {
    const float* query = (const float*)d_in[0];
    const float* key   = (const float*)d_in[1];
    const float* value = (const float*)d_in[2];
    const float* Wq    = (const float*)d_in[3];
    const float* Wk    = (const float*)d_in[4];
    const float* Wv    = (const float*)d_in[5];
    const float* Wo    = (const float*)d_in[6];
    const float* bo    = (const float*)d_in[7];

    float* out_attn = (float*)d_out;                       // [B,Q,512]
    float* out_w    = (float*)d_out + (size_t)Bc*Qn*DQ;    // [B,H,Q,K]

    float *qs, *ksp, *vsp, *qop, *qnp, *lp, *knp;
    cudaGetSymbolAddress((void**)&qs,  g_qs);
    cudaGetSymbolAddress((void**)&ksp, g_ks);
    cudaGetSymbolAddress((void**)&vsp, g_vs);
    cudaGetSymbolAddress((void**)&qop, g_qo);
    cudaGetSymbolAddress((void**)&qnp, g_qn);
    cudaGetSymbolAddress((void**)&lp,  g_l);
    cudaGetSymbolAddress((void**)&knp, g_knm);

    const int M = Bc * Qn;          // 8192
    const float scaling = 0.17677669529663687f;  // 1/sqrt(32)

    // 1) projections
    {
        dim3 grid(M / 64, INNER / 64);
        sgemm_kernel<<<grid, 256>>>(query, Wq, nullptr, qs,  M, INNER, DQ, scaling);
        sgemm_kernel<<<grid, 256>>>(key,   Wk, nullptr, ksp, M, INNER, DQ, 1.f);
        sgemm_kernel<<<grid, 256>>>(value, Wv, nullptr, vsp, M, INNER, DQ, 1.f);
    }
    // 2) softmax shift bound: c = ||q|| * max||k||
    {
        qnorm_kernel<<<Bc * Qn * NH / 256, 256>>>(qs, qnp);
        knorm_kernel<<<Bc * NH, 256>>>(ksp, knp);
    }
    // 3) flash kernel: l + PV output (no score store, no max machinery)
    {
        cudaFuncSetAttribute(flash_kernel, cudaFuncAttributeMaxDynamicSharedMemorySize,
                             SMEM_BYTES);
        dim3 grid(Qn / 128, NH, Bc);
        flash_kernel<<<grid, 256, SMEM_BYTES>>>(qs, ksp, vsp, qnp, knp, qop, lp);
    }
    // 4) weights kernel: recompute scores, write normalized weights once
    {
        dim3 grid(Qn / 128, NH, Bc);
        weights_kernel<<<grid, 256>>>(qs, ksp, qnp, knp, lp, out_w);
    }
    // 5) output projection + bias
    {
        dim3 grid(M / 64, DQ / 64);
        sgemm_kernel<<<grid, 256>>>(qop, Wo, bo, out_attn, M, DQ, INNER, 1.f);
    }
}

// round 11
// speedup vs baseline: 1.7081x; 1.7081x over previous
#include <cuda_runtime.h>
#include <cuda_bf16.h>
#include <math.h>
#include <stdint.h>

// Problem constants
#define Bc   2
#define Qn   4096
#define Kn   4096
#define DQ   512
#define NH   8
#define DH   32
#define INNER (NH*DH)   // 256

// ---------------- scratch (no allocs allowed) ----------------
__device__ float g_qs[Bc*Qn*INNER];   // projected, scaled q  [B,Q,256]
__device__ float g_ks[Bc*Kn*INNER];   // projected k          [B,K,256]
__device__ float g_vs[Bc*Kn*INNER];   // projected v          [B,K,256]
__device__ float g_qo[Bc*Qn*INNER];   // attention out (pre Wo) [B,Q,256]
__device__ float g_qn[Bc*NH*Qn];      // ||q_row||  -> shift c
__device__ float g_l[Bc*NH*Qn];       // row sum-exp vs shift c
__device__ float g_knm[Bc*NH];        // max_k ||k_row||

// ---------------- generic fp32 SGEMM: C = scale*(A@B) + bias ----------------
__global__ void sgemm_kernel(const float* __restrict__ A, const float* __restrict__ B,
                             const float* __restrict__ bias, float* __restrict__ C,
                             int M, int N, int K, float scale) {
    __shared__ float As[16][68];
    __shared__ float Bs[16][64];
    int tid = threadIdx.x;
    int tx = tid & 15, ty = tid >> 4;
    int bm = blockIdx.x * 64, bn = blockIdx.y * 64;

    float acc[4][4];
#pragma unroll
    for (int i = 0; i < 4; i++)
#pragma unroll
        for (int j = 0; j < 4; j++) acc[i][j] = 0.f;

    for (int k0 = 0; k0 < K; k0 += 16) {
        {
            int m = tid >> 2, kq = (tid & 3) << 2;
            float4 a = *(const float4*)&A[(size_t)(bm + m) * K + k0 + kq];
            As[kq + 0][m] = a.x; As[kq + 1][m] = a.y;
            As[kq + 2][m] = a.z; As[kq + 3][m] = a.w;
        }
        {
            int kk = tid >> 4, nq = (tid & 15) << 2;
            *(float4*)&Bs[kk][nq] = *(const float4*)&B[(size_t)(k0 + kk) * N + bn + nq];
        }
        __syncthreads();
#pragma unroll
        for (int kk = 0; kk < 16; kk++) {
            float4 a4 = *(const float4*)&As[kk][ty * 4];
            float4 b4 = *(const float4*)&Bs[kk][tx * 4];
            float av[4] = {a4.x, a4.y, a4.z, a4.w};
            float bv[4] = {b4.x, b4.y, b4.z, b4.w};
#pragma unroll
            for (int i = 0; i < 4; i++)
#pragma unroll
                for (int j = 0; j < 4; j++) acc[i][j] += av[i] * bv[j];
        }
        __syncthreads();
    }
#pragma unroll
    for (int i = 0; i < 4; i++) {
        int row = bm + ty * 4 + i;
        int col = bn + tx * 4;
        float4 o;
        o.x = acc[i][0] * scale; o.y = acc[i][1] * scale;
        o.z = acc[i][2] * scale; o.w = acc[i][3] * scale;
        if (bias) {
            o.x += bias[col + 0]; o.y += bias[col + 1];
            o.z += bias[col + 2]; o.w += bias[col + 3];
        }
        *(float4*)&C[(size_t)row * N + col] = o;
    }
}

// ---------------- norm kernels (softmax shift bound) ----------------
__global__ void qnorm_kernel(const float* __restrict__ q, float* __restrict__ qn) {
    int t = blockIdx.x * 256 + threadIdx.x;
    int h = t & 7, bq = t >> 3;
    int b = bq >> 12, qq = bq & 4095;
    const float* p = q + (size_t)bq * INNER + h * DH;
    float s = 0.f;
#pragma unroll
    for (int i = 0; i < 8; i++) {
        float4 v = *(const float4*)(p + i * 4);
        s += v.x * v.x + v.y * v.y + v.z * v.z + v.w * v.w;
    }
    qn[((b * NH + h) * Qn) + qq] = sqrtf(s);
}

__global__ void knorm_kernel(const float* __restrict__ k, float* __restrict__ knm) {
    int bh = blockIdx.x;
    int b = bh >> 3, h = bh & 7;
    float mx = 0.f;
    for (int row = threadIdx.x; row < Kn; row += 256) {
        const float* p = k + ((size_t)(b * Kn) + row) * INNER + h * DH;
        float s = 0.f;
#pragma unroll
        for (int i = 0; i < 8; i++) {
            float4 v = *(const float4*)(p + i * 4);
            s += v.x * v.x + v.y * v.y + v.z * v.z + v.w * v.w;
        }
        mx = fmaxf(mx, s);
    }
    __shared__ float red[256];
    red[threadIdx.x] = mx;
    __syncthreads();
    for (int s = 128; s; s >>= 1) {
        if (threadIdx.x < s) red[threadIdx.x] = fmaxf(red[threadIdx.x], red[threadIdx.x + s]);
        __syncthreads();
    }
    if (threadIdx.x == 0) knm[bh] = sqrtf(red[0]);
}

// ================= mma.sync bf16 plumbing (sm_80+, no 'a' features) ========
__device__ __forceinline__ void mma_bf16(float c[4], const uint32_t a[4],
                                         const uint32_t b[2]) {
    asm volatile(
        "mma.sync.aligned.m16n8k16.row.col.f32.bf16.bf16.f32 "
        "{%0,%1,%2,%3}, {%4,%5,%6,%7}, {%8,%9}, {%0,%1,%2,%3};"
        : "+f"(c[0]), "+f"(c[1]), "+f"(c[2]), "+f"(c[3])
        : "r"(a[0]), "r"(a[1]), "r"(a[2]), "r"(a[3]), "r"(b[0]), "r"(b[1]));
}

__device__ __forceinline__ uint32_t bfpack(float x, float y) {
    __nv_bfloat162 t;
    t.x = __float2bfloat16(x);
    t.y = __float2bfloat16(y);
    return *(uint32_t*)&t;
}
// split x into hi (bf16-representable) returning hi as float
__device__ __forceinline__ float bfhi(float x) {
    return __bfloat162float(__float2bfloat16(x));
}

// ---------------- fused attention, mma.sync bf16x3 compensated --------------
// PASS 0: l = sum_k exp(s - c).   PASS 1: weights = exp(s - c - ln l) + PV.
// grid = (Qn/128, NH, Bc), 256 threads (8 warps x 16 q-rows), chunk = 128 kk.
//
// smem word offsets (pair-major layouts, strides == 8 mod 32 -> conflict-free)
#define S_QH 0                    // [16 kd-pairs][128 rows] stride 136
#define S_QL 2176
#define S_KH 4352                 // [16 kd-pairs][128 cols] stride 136
#define S_KL 6528
#define S_VH 8704                 // [64 kk-pairs][32 d]     stride 40
#define S_VL 11264
#define SM_WORDS 13824
#define SM_BYTES (SM_WORDS*4)     // 55296

template<int PASS>
__global__ void __launch_bounds__(256, 2)
fa_kernel(const float* __restrict__ qs, const float* __restrict__ ks,
          const float* __restrict__ vs, const float* __restrict__ qn,
          const float* __restrict__ knm, float* __restrict__ lg,
          float* __restrict__ wout, float* __restrict__ qo) {
    extern __shared__ float sm[];
    uint32_t* qhw = (uint32_t*)(sm + S_QH);
    uint32_t* qlw = (uint32_t*)(sm + S_QL);
    uint32_t* khw = (uint32_t*)(sm + S_KH);
    uint32_t* klw = (uint32_t*)(sm + S_KL);
    uint32_t* vhw = (uint32_t*)(sm + S_VH);
    uint32_t* vlw = (uint32_t*)(sm + S_VL);

    const int b = blockIdx.z, h = blockIdx.y, q0 = blockIdx.x * 128;
    const int tid = threadIdx.x;
    const int warp = tid >> 5, lane = tid & 31;
    const int g = lane >> 2, qd = lane & 3;       // groupID, thread-in-group
    const size_t bh = (size_t)(b * NH + h);

    // ---- stage Q tile: hi/lo bf16 pairs, layout [kd-pair][row] ----
#pragma unroll
    for (int i = 0; i < 8; i++) {
        int idx = tid + i * 256;                  // 2048 = 16 wp x 128 rows
        int wp = idx >> 7, r = idx & 127;
        float2 v = *(const float2*)&qs[((size_t)(b * Qn) + q0 + r) * INNER + h * DH + 2 * wp];
        float h0 = bfhi(v.x), h1 = bfhi(v.y);
        qhw[wp * 136 + r] = bfpack(h0, h1);
        qlw[wp * 136 + r] = bfpack(v.x - h0, v.y - h1);
    }

    // per-thread rows and shifts
    const int r0 = warp * 16 + g;                 // this thread's rows: r0, r0+8
    float cp0, cp1;
    {
        float km = knm[bh];
        cp0 = qn[bh * Qn + q0 + r0] * km;
        cp1 = qn[bh * Qn + q0 + r0 + 8] * km;
        if (PASS) {
            cp0 += __logf(lg[bh * Qn + q0 + r0]);
            cp1 += __logf(lg[bh * Qn + q0 + r0 + 8]);
        }
    }
    float l0 = 0.f, l1 = 0.f;

    __syncthreads();

    // ---- Q A-fragments (persist whole kernel) ----
    uint32_t aH[2][4], aL[2][4];
#pragma unroll
    for (int kst = 0; kst < 2; kst++) {
        int ba = (kst * 8 + qd) * 136 + warp * 16 + g;
        aH[kst][0] = qhw[ba];            aH[kst][1] = qhw[ba + 8];
        aH[kst][2] = qhw[ba + 4 * 136];  aH[kst][3] = qhw[ba + 4 * 136 + 8];
        aL[kst][0] = qlw[ba];            aL[kst][1] = qlw[ba + 8];
        aL[kst][2] = qlw[ba + 4 * 136];  aL[kst][3] = qlw[ba + 4 * 136 + 8];
    }

    float o[4][4];
#pragma unroll
    for (int dt = 0; dt < 4; dt++)
#pragma unroll
        for (int j = 0; j < 4; j++) o[dt][j] = 0.f;

    for (int c = 0; c < Kn / 128; c++) {
        const int c0 = c * 128;
        __syncthreads();   // previous chunk's smem reads done

        // ---- stage K chunk: [kd-pair][col] hi/lo ----
#pragma unroll
        for (int i = 0; i < 8; i++) {
            int idx = tid + i * 256;
            int wp = idx >> 7, col = idx & 127;
            float2 v = *(const float2*)&ks[((size_t)(b * Kn) + c0 + col) * INNER + h * DH + 2 * wp];
            float h0 = bfhi(v.x), h1 = bfhi(v.y);
            khw[wp * 136 + col] = bfpack(h0, h1);
            klw[wp * 136 + col] = bfpack(v.x - h0, v.y - h1);
        }
        if (PASS) {
            // ---- stage V chunk: [kk-pair][d] hi/lo ----
#pragma unroll
            for (int i = 0; i < 8; i++) {
                int idx = tid + i * 256;          // 2048 = 64 kp x 32 d
                int kp = idx >> 5, d = idx & 31;
                float x0 = vs[((size_t)(b * Kn) + c0 + 2 * kp) * INNER + h * DH + d];
                float x1 = vs[((size_t)(b * Kn) + c0 + 2 * kp + 1) * INNER + h * DH + d];
                float h0 = bfhi(x0), h1 = bfhi(x1);
                vhw[kp * 40 + d] = bfpack(h0, h1);
                vlw[kp * 40 + d] = bfpack(x0 - h0, x1 - h1);
            }
        }
        __syncthreads();

        // ---- 8 kk-blocks of 16 ----
#pragma unroll 2
        for (int ksb = 0; ksb < 8; ksb++) {
            uint32_t pH[4], pL[4];
#pragma unroll
            for (int t = 0; t < 2; t++) {
                const int nt = ksb * 2 + t;       // score n-tile (8 cols)
                float cacc[4] = {0.f, 0.f, 0.f, 0.f};
#pragma unroll
                for (int kst = 0; kst < 2; kst++) {
                    uint32_t bH[2], bL[2];
                    int ba = (kst * 8 + qd) * 136 + nt * 8 + g;
                    bH[0] = khw[ba]; bH[1] = khw[ba + 4 * 136];
                    bL[0] = klw[ba]; bL[1] = klw[ba + 4 * 136];
                    mma_bf16(cacc, aH[kst], bH);
                    mma_bf16(cacc, aH[kst], bL);
                    mma_bf16(cacc, aL[kst], bH);
                }
                float p0 = __expf(cacc[0] - cp0);
                float p1 = __expf(cacc[1] - cp0);
                float p2 = __expf(cacc[2] - cp1);
                float p3 = __expf(cacc[3] - cp1);
                l0 += p0 + p1;
                l1 += p2 + p3;
                if (PASS) {
                    // final normalized weights, streamed once
                    size_t wb = (bh * Qn + q0 + r0) * (size_t)Kn + c0 + nt * 8 + qd * 2;
                    *(float2*)&wout[wb] = make_float2(p0, p1);
                    *(float2*)&wout[wb + (size_t)8 * Kn] = make_float2(p2, p3);
                    // repack P into A-fragments (C-frag layout == A-frag sublayout)
                    float h0 = bfhi(p0), h1 = bfhi(p1);
                    float h2 = bfhi(p2), h3 = bfhi(p3);
                    pH[2 * t + 0] = bfpack(h0, h1);
                    pH[2 * t + 1] = bfpack(h2, h3);
                    pL[2 * t + 0] = bfpack(p0 - h0, p1 - h1);
                    pL[2 * t + 1] = bfpack(p2 - h2, p3 - h3);
                }
            }
            if (PASS) {
                // ---- PV: O += P * V over this kk-block ----
#pragma unroll
                for (int dt = 0; dt < 4; dt++) {
                    uint32_t bH[2], bL[2];
                    int ba = (ksb * 8 + qd) * 40 + dt * 8 + g;
                    bH[0] = vhw[ba]; bH[1] = vhw[ba + 4 * 40];
                    bL[0] = vlw[ba]; bL[1] = vlw[ba + 4 * 40];
                    mma_bf16(o[dt], pH, bH);
                    mma_bf16(o[dt], pH, bL);
                    mma_bf16(o[dt], pL, bH);
                }
            }
        }
    }

    if (PASS == 0) {
        // reduce l over the 4 lanes of each row group
        l0 += __shfl_xor_sync(0xffffffffu, l0, 1);
        l0 += __shfl_xor_sync(0xffffffffu, l0, 2);
        l1 += __shfl_xor_sync(0xffffffffu, l1, 1);
        l1 += __shfl_xor_sync(0xffffffffu, l1, 2);
        if (qd == 0) {
            lg[bh * Qn + q0 + r0] = l0;
            lg[bh * Qn + q0 + r0 + 8] = l1;
        }
    } else {
        // O already normalized (shift included ln l)
        float* op0 = qo + ((size_t)(b * Qn) + q0 + r0) * INNER + h * DH;
        float* op1 = qo + ((size_t)(b * Qn) + q0 + r0 + 8) * INNER + h * DH;
#pragma unroll
        for (int dt = 0; dt < 4; dt++) {
            *(float2*)&op0[dt * 8 + qd * 2] = make_float2(o[dt][0], o[dt][1]);
            *(float2*)&op1[dt * 8 + qd * 2] = make_float2(o[dt][2], o[dt][3]);
        }
    }
}

// ---------------- launch ----------------
extern "C" void kernel_launch(void* const* d_in, const int* in_sizes, int n_in,
                              void* d_out, int out_size) {
    const float* query = (const float*)d_in[0];
    const float* key   = (const float*)d_in[1];
    const float* value = (const float*)d_in[2];
    const float* Wq    = (const float*)d_in[3];
    const float* Wk    = (const float*)d_in[4];
    const float* Wv    = (const float*)d_in[5];
    const float* Wo    = (const float*)d_in[6];
    const float* bo    = (const float*)d_in[7];

    float* out_attn = (float*)d_out;                       // [B,Q,512]
    float* out_w    = (float*)d_out + (size_t)Bc*Qn*DQ;    // [B,H,Q,K]

    float *qs, *ksp, *vsp, *qop, *qnp, *lp, *knp;
    cudaGetSymbolAddress((void**)&qs,  g_qs);
    cudaGetSymbolAddress((void**)&ksp, g_ks);
    cudaGetSymbolAddress((void**)&vsp, g_vs);
    cudaGetSymbolAddress((void**)&qop, g_qo);
    cudaGetSymbolAddress((void**)&qnp, g_qn);
    cudaGetSymbolAddress((void**)&lp,  g_l);
    cudaGetSymbolAddress((void**)&knp, g_knm);

    const int M = Bc * Qn;          // 8192
    const float scaling = 0.17677669529663687f;  // 1/sqrt(32)

    // 1) projections
    {
        dim3 grid(M / 64, INNER / 64);
        sgemm_kernel<<<grid, 256>>>(query, Wq, nullptr, qs,  M, INNER, DQ, scaling);
        sgemm_kernel<<<grid, 256>>>(key,   Wk, nullptr, ksp, M, INNER, DQ, 1.f);
        sgemm_kernel<<<grid, 256>>>(value, Wv, nullptr, vsp, M, INNER, DQ, 1.f);
    }
    // 2) softmax shift bound: c = ||q|| * max||k||
    {
        qnorm_kernel<<<Bc * Qn * NH / 256, 256>>>(qs, qnp);
        knorm_kernel<<<Bc * NH, 256>>>(ksp, knp);
    }
    // 3) pass A: row sums l;  pass B: weights + PV (tensor cores via mma.sync)
    {
        cudaFuncSetAttribute(fa_kernel<0>, cudaFuncAttributeMaxDynamicSharedMemorySize, SM_BYTES);
        cudaFuncSetAttribute(fa_kernel<1>, cudaFuncAttributeMaxDynamicSharedMemorySize, SM_BYTES);
        dim3 grid(Qn / 128, NH, Bc);
        fa_kernel<0><<<grid, 256, SM_BYTES>>>(qs, ksp, vsp, qnp, knp, lp, out_w, qop);
        fa_kernel<1><<<grid, 256, SM_BYTES>>>(qs, ksp, vsp, qnp, knp, lp, out_w, qop);
    }
    // 4) output projection + bias
    {
        dim3 grid(M / 64, DQ / 64);
        sgemm_kernel<<<grid, 256>>>(qop, Wo, bo, out_attn, M, DQ, INNER, 1.f);
    }
}

// round 12
// speedup vs baseline: 1.7591x; 1.0299x over previous
#include <cuda_runtime.h>
#include <cuda_bf16.h>
#include <math.h>
#include <stdint.h>

// Problem constants
#define Bc   2
#define Qn   4096
#define Kn   4096
#define DQ   512
#define NH   8
#define DH   32
#define INNER (NH*DH)   // 256

// ---------------- scratch (no allocs allowed) ----------------
__device__ float g_qs[Bc*Qn*INNER];   // projected, scaled q  [B,Q,256]
__device__ float g_ks[Bc*Kn*INNER];   // projected k          [B,K,256]
__device__ float g_vs[Bc*Kn*INNER];   // projected v          [B,K,256]
__device__ float g_qo[Bc*Qn*INNER];   // attention out (pre Wo) [B,Q,256]
__device__ float g_qn[Bc*NH*Qn];      // ||q_row||  -> shift c
__device__ float g_l[Bc*NH*Qn];       // row sum-exp vs shift c
__device__ float g_knm[Bc*NH];        // max_k ||k_row||

// ================= mma.sync bf16 plumbing (sm_80+, no 'a' features) ========
__device__ __forceinline__ void mma_bf16(float c[4], const uint32_t a[4],
                                         const uint32_t b[2]) {
    asm volatile(
        "mma.sync.aligned.m16n8k16.row.col.f32.bf16.bf16.f32 "
        "{%0,%1,%2,%3}, {%4,%5,%6,%7}, {%8,%9}, {%0,%1,%2,%3};"
        : "+f"(c[0]), "+f"(c[1]), "+f"(c[2]), "+f"(c[3])
        : "r"(a[0]), "r"(a[1]), "r"(a[2]), "r"(a[3]), "r"(b[0]), "r"(b[1]));
}

__device__ __forceinline__ uint32_t bfpack(float x, float y) {
    __nv_bfloat162 t;
    t.x = __float2bfloat16(x);
    t.y = __float2bfloat16(y);
    return *(uint32_t*)&t;
}
__device__ __forceinline__ float bfhi(float x) {
    return __bfloat162float(__float2bfloat16(x));
}

// ---------------- tensor-core GEMM, bf16x3: C = scale*(A@W) (+bias) --------
// A[M,K] row-major, W[K,N] row-major, C[M,N]. Tile 128x64, 256 thr, 8 warps.
// Fragment layouts identical to fa_kernel (validated).
#define G_AH 0        // [16 kd-pairs][128 rows] stride 136
#define G_AL 2176
#define G_BH 4352     // [16 kd-pairs][64 cols]  stride 72
#define G_BL 5504
#define G_WORDS 6656  // 26624 B

__global__ void __launch_bounds__(256)
gemm_tc(const float* __restrict__ A, const float* __restrict__ W,
        const float* __restrict__ bias, float* __restrict__ C,
        int M, int N, int K, float scale) {
    __shared__ float sm[G_WORDS];
    uint32_t* ahw = (uint32_t*)(sm + G_AH);
    uint32_t* alw = (uint32_t*)(sm + G_AL);
    uint32_t* bhw = (uint32_t*)(sm + G_BH);
    uint32_t* blw = (uint32_t*)(sm + G_BL);

    const int bm = blockIdx.x * 128, bn = blockIdx.y * 64;
    const int tid = threadIdx.x;
    const int warp = tid >> 5, lane = tid & 31;
    const int g = lane >> 2, qd = lane & 3;
    const int r0 = warp * 16 + g;

    float o[8][4];
#pragma unroll
    for (int nt = 0; nt < 8; nt++)
#pragma unroll
        for (int j = 0; j < 4; j++) o[nt][j] = 0.f;

    for (int k0 = 0; k0 < K; k0 += 32) {
        __syncthreads();
        // stage A chunk: 128 rows x 16 pairs, hi/lo
#pragma unroll
        for (int i = 0; i < 8; i++) {
            int idx = tid + i * 256;
            int wp = idx >> 7, r = idx & 127;
            float2 v = *(const float2*)&A[(size_t)(bm + r) * K + k0 + 2 * wp];
            float h0 = bfhi(v.x), h1 = bfhi(v.y);
            ahw[wp * 136 + r] = bfpack(h0, h1);
            alw[wp * 136 + r] = bfpack(v.x - h0, v.y - h1);
        }
        // stage B chunk: 64 cols x 16 pairs (k-major per col), hi/lo
#pragma unroll
        for (int i = 0; i < 4; i++) {
            int idx = tid + i * 256;
            int wp = idx >> 6, n = idx & 63;
            float x0 = W[(size_t)(k0 + 2 * wp) * N + bn + n];
            float x1 = W[(size_t)(k0 + 2 * wp + 1) * N + bn + n];
            float h0 = bfhi(x0), h1 = bfhi(x1);
            bhw[wp * 72 + n] = bfpack(h0, h1);
            blw[wp * 72 + n] = bfpack(x0 - h0, x1 - h1);
        }
        __syncthreads();

        // A fragments for this chunk
        uint32_t aH[2][4], aL[2][4];
#pragma unroll
        for (int kst = 0; kst < 2; kst++) {
            int ba = (kst * 8 + qd) * 136 + r0;
            aH[kst][0] = ahw[ba];            aH[kst][1] = ahw[ba + 8];
            aH[kst][2] = ahw[ba + 4 * 136];  aH[kst][3] = ahw[ba + 4 * 136 + 8];
            aL[kst][0] = alw[ba];            aL[kst][1] = alw[ba + 8];
            aL[kst][2] = alw[ba + 4 * 136];  aL[kst][3] = alw[ba + 4 * 136 + 8];
        }
#pragma unroll
        for (int nt = 0; nt < 8; nt++) {
#pragma unroll
            for (int kst = 0; kst < 2; kst++) {
                uint32_t bH[2], bL[2];
                int ba = (kst * 8 + qd) * 72 + nt * 8 + g;
                bH[0] = bhw[ba]; bH[1] = bhw[ba + 4 * 72];
                bL[0] = blw[ba]; bL[1] = blw[ba + 4 * 72];
                mma_bf16(o[nt], aH[kst], bH);
                mma_bf16(o[nt], aH[kst], bL);
                mma_bf16(o[nt], aL[kst], bH);
            }
        }
    }

    // epilogue
#pragma unroll
    for (int nt = 0; nt < 8; nt++) {
        int col = bn + nt * 8 + qd * 2;
        float b0 = 0.f, b1 = 0.f;
        if (bias) { b0 = bias[col]; b1 = bias[col + 1]; }
        *(float2*)&C[(size_t)(bm + r0) * N + col] =
            make_float2(o[nt][0] * scale + b0, o[nt][1] * scale + b1);
        *(float2*)&C[(size_t)(bm + r0 + 8) * N + col] =
            make_float2(o[nt][2] * scale + b0, o[nt][3] * scale + b1);
    }
}

// ---------------- norm kernels (softmax shift bound) ----------------
__global__ void qnorm_kernel(const float* __restrict__ q, float* __restrict__ qn) {
    int t = blockIdx.x * 256 + threadIdx.x;
    int h = t & 7, bq = t >> 3;
    int b = bq >> 12, qq = bq & 4095;
    const float* p = q + (size_t)bq * INNER + h * DH;
    float s = 0.f;
#pragma unroll
    for (int i = 0; i < 8; i++) {
        float4 v = *(const float4*)(p + i * 4);
        s += v.x * v.x + v.y * v.y + v.z * v.z + v.w * v.w;
    }
    qn[((b * NH + h) * Qn) + qq] = sqrtf(s);
}

__global__ void knorm_kernel(const float* __restrict__ k, float* __restrict__ knm) {
    int bh = blockIdx.x;
    int b = bh >> 3, h = bh & 7;
    float mx = 0.f;
    for (int row = threadIdx.x; row < Kn; row += 256) {
        const float* p = k + ((size_t)(b * Kn) + row) * INNER + h * DH;
        float s = 0.f;
#pragma unroll
        for (int i = 0; i < 8; i++) {
            float4 v = *(const float4*)(p + i * 4);
            s += v.x * v.x + v.y * v.y + v.z * v.z + v.w * v.w;
        }
        mx = fmaxf(mx, s);
    }
    __shared__ float red[256];
    red[threadIdx.x] = mx;
    __syncthreads();
    for (int s = 128; s; s >>= 1) {
        if (threadIdx.x < s) red[threadIdx.x] = fmaxf(red[threadIdx.x], red[threadIdx.x + s]);
        __syncthreads();
    }
    if (threadIdx.x == 0) knm[bh] = sqrtf(red[0]);
}

// ---------------- fused attention, mma.sync bf16x3 compensated --------------
// PASS 0: l = sum_k exp(s - c).   PASS 1: weights = exp(s - c - ln l) + PV.
// grid = (Qn/128, NH, Bc), 256 threads (8 warps x 16 q-rows), chunk = 128 kk.
#define S_QH 0                    // [16 kd-pairs][128 rows] stride 136
#define S_QL 2176
#define S_KH 4352                 // [16 kd-pairs][128 cols] stride 136
#define S_KL 6528
#define S_VH 8704                 // [64 kk-pairs][32 d]     stride 40
#define S_VL 11264
#define SM_WORDS 13824
#define SM_BYTES (SM_WORDS*4)     // 55296

template<int PASS>
__global__ void __launch_bounds__(256, 2)
fa_kernel(const float* __restrict__ qs, const float* __restrict__ ks,
          const float* __restrict__ vs, const float* __restrict__ qn,
          const float* __restrict__ knm, float* __restrict__ lg,
          float* __restrict__ wout, float* __restrict__ qo) {
    extern __shared__ float sm[];
    uint32_t* qhw = (uint32_t*)(sm + S_QH);
    uint32_t* qlw = (uint32_t*)(sm + S_QL);
    uint32_t* khw = (uint32_t*)(sm + S_KH);
    uint32_t* klw = (uint32_t*)(sm + S_KL);
    uint32_t* vhw = (uint32_t*)(sm + S_VH);
    uint32_t* vlw = (uint32_t*)(sm + S_VL);

    const int b = blockIdx.z, h = blockIdx.y, q0 = blockIdx.x * 128;
    const int tid = threadIdx.x;
    const int warp = tid >> 5, lane = tid & 31;
    const int g = lane >> 2, qd = lane & 3;
    const size_t bh = (size_t)(b * NH + h);

    // ---- stage Q tile: hi/lo bf16 pairs, layout [kd-pair][row] ----
#pragma unroll
    for (int i = 0; i < 8; i++) {
        int idx = tid + i * 256;
        int wp = idx >> 7, r = idx & 127;
        float2 v = *(const float2*)&qs[((size_t)(b * Qn) + q0 + r) * INNER + h * DH + 2 * wp];
        float h0 = bfhi(v.x), h1 = bfhi(v.y);
        qhw[wp * 136 + r] = bfpack(h0, h1);
        qlw[wp * 136 + r] = bfpack(v.x - h0, v.y - h1);
    }

    const int r0 = warp * 16 + g;
    float cp0, cp1;
    {
        float km = knm[bh];
        cp0 = qn[bh * Qn + q0 + r0] * km;
        cp1 = qn[bh * Qn + q0 + r0 + 8] * km;
        if (PASS) {
            cp0 += __logf(lg[bh * Qn + q0 + r0]);
            cp1 += __logf(lg[bh * Qn + q0 + r0 + 8]);
        }
    }
    float l0 = 0.f, l1 = 0.f;

    __syncthreads();

    // ---- Q A-fragments (persist whole kernel) ----
    uint32_t aH[2][4], aL[2][4];
#pragma unroll
    for (int kst = 0; kst < 2; kst++) {
        int ba = (kst * 8 + qd) * 136 + warp * 16 + g;
        aH[kst][0] = qhw[ba];            aH[kst][1] = qhw[ba + 8];
        aH[kst][2] = qhw[ba + 4 * 136];  aH[kst][3] = qhw[ba + 4 * 136 + 8];
        aL[kst][0] = qlw[ba];            aL[kst][1] = qlw[ba + 8];
        aL[kst][2] = qlw[ba + 4 * 136];  aL[kst][3] = qlw[ba + 4 * 136 + 8];
    }

    float o[4][4];
#pragma unroll
    for (int dt = 0; dt < 4; dt++)
#pragma unroll
        for (int j = 0; j < 4; j++) o[dt][j] = 0.f;

    for (int c = 0; c < Kn / 128; c++) {
        const int c0 = c * 128;
        __syncthreads();

        // ---- stage K chunk ----
#pragma unroll
        for (int i = 0; i < 8; i++) {
            int idx = tid + i * 256;
            int wp = idx >> 7, col = idx & 127;
            float2 v = *(const float2*)&ks[((size_t)(b * Kn) + c0 + col) * INNER + h * DH + 2 * wp];
            float h0 = bfhi(v.x), h1 = bfhi(v.y);
            khw[wp * 136 + col] = bfpack(h0, h1);
            klw[wp * 136 + col] = bfpack(v.x - h0, v.y - h1);
        }
        if (PASS) {
            // ---- stage V chunk ----
#pragma unroll
            for (int i = 0; i < 8; i++) {
                int idx = tid + i * 256;
                int kp = idx >> 5, d = idx & 31;
                float x0 = vs[((size_t)(b * Kn) + c0 + 2 * kp) * INNER + h * DH + d];
                float x1 = vs[((size_t)(b * Kn) + c0 + 2 * kp + 1) * INNER + h * DH + d];
                float h0 = bfhi(x0), h1 = bfhi(x1);
                vhw[kp * 40 + d] = bfpack(h0, h1);
                vlw[kp * 40 + d] = bfpack(x0 - h0, x1 - h1);
            }
        }
        __syncthreads();

#pragma unroll 2
        for (int ksb = 0; ksb < 8; ksb++) {
            uint32_t pH[4], pL[4];
#pragma unroll
            for (int t = 0; t < 2; t++) {
                const int nt = ksb * 2 + t;
                float cacc[4] = {0.f, 0.f, 0.f, 0.f};
#pragma unroll
                for (int kst = 0; kst < 2; kst++) {
                    uint32_t bH[2], bL[2];
                    int ba = (kst * 8 + qd) * 136 + nt * 8 + g;
                    bH[0] = khw[ba]; bH[1] = khw[ba + 4 * 136];
                    bL[0] = klw[ba]; bL[1] = klw[ba + 4 * 136];
                    mma_bf16(cacc, aH[kst], bH);
                    mma_bf16(cacc, aH[kst], bL);
                    mma_bf16(cacc, aL[kst], bH);
                }
                float p0 = __expf(cacc[0] - cp0);
                float p1 = __expf(cacc[1] - cp0);
                float p2 = __expf(cacc[2] - cp1);
                float p3 = __expf(cacc[3] - cp1);
                l0 += p0 + p1;
                l1 += p2 + p3;
                if (PASS) {
                    size_t wb = (bh * Qn + q0 + r0) * (size_t)Kn + c0 + nt * 8 + qd * 2;
                    *(float2*)&wout[wb] = make_float2(p0, p1);
                    *(float2*)&wout[wb + (size_t)8 * Kn] = make_float2(p2, p3);
                    float h0 = bfhi(p0), h1 = bfhi(p1);
                    float h2 = bfhi(p2), h3 = bfhi(p3);
                    pH[2 * t + 0] = bfpack(h0, h1);
                    pH[2 * t + 1] = bfpack(h2, h3);
                    pL[2 * t + 0] = bfpack(p0 - h0, p1 - h1);
                    pL[2 * t + 1] = bfpack(p2 - h2, p3 - h3);
                }
            }
            if (PASS) {
#pragma unroll
                for (int dt = 0; dt < 4; dt++) {
                    uint32_t bH[2], bL[2];
                    int ba = (ksb * 8 + qd) * 40 + dt * 8 + g;
                    bH[0] = vhw[ba]; bH[1] = vhw[ba + 4 * 40];
                    bL[0] = vlw[ba]; bL[1] = vlw[ba + 4 * 40];
                    mma_bf16(o[dt], pH, bH);
                    mma_bf16(o[dt], pH, bL);
                    mma_bf16(o[dt], pL, bH);
                }
            }
        }
    }

    if (PASS == 0) {
        l0 += __shfl_xor_sync(0xffffffffu, l0, 1);
        l0 += __shfl_xor_sync(0xffffffffu, l0, 2);
        l1 += __shfl_xor_sync(0xffffffffu, l1, 1);
        l1 += __shfl_xor_sync(0xffffffffu, l1, 2);
        if (qd == 0) {
            lg[bh * Qn + q0 + r0] = l0;
            lg[bh * Qn + q0 + r0 + 8] = l1;
        }
    } else {
        float* op0 = qo + ((size_t)(b * Qn) + q0 + r0) * INNER + h * DH;
        float* op1 = qo + ((size_t)(b * Qn) + q0 + r0 + 8) * INNER + h * DH;
#pragma unroll
        for (int dt = 0; dt < 4; dt++) {
            *(float2*)&op0[dt * 8 + qd * 2] = make_float2(o[dt][0], o[dt][1]);
            *(float2*)&op1[dt * 8 + qd * 2] = make_float2(o[dt][2], o[dt][3]);
        }
    }
}

// ---------------- launch ----------------
extern "C" void kernel_launch(void* const* d_in, const int* in_sizes, int n_in,
                              void* d_out, int out_size) {
    const float* query = (const float*)d_in[0];
    const float* key   = (const float*)d_in[1];
    const float* value = (const float*)d_in[2];
    const float* Wq    = (const float*)d_in[3];
    const float* Wk    = (const float*)d_in[4];
    const float* Wv    = (const float*)d_in[5];
    const float* Wo    = (const float*)d_in[6];
    const float* bo    = (const float*)d_in[7];

    float* out_attn = (float*)d_out;                       // [B,Q,512]
    float* out_w    = (float*)d_out + (size_t)Bc*Qn*DQ;    // [B,H,Q,K]

    float *qs, *ksp, *vsp, *qop, *qnp, *lp, *knp;
    cudaGetSymbolAddress((void**)&qs,  g_qs);
    cudaGetSymbolAddress((void**)&ksp, g_ks);
    cudaGetSymbolAddress((void**)&vsp, g_vs);
    cudaGetSymbolAddress((void**)&qop, g_qo);
    cudaGetSymbolAddress((void**)&qnp, g_qn);
    cudaGetSymbolAddress((void**)&lp,  g_l);
    cudaGetSymbolAddress((void**)&knp, g_knm);

    const int M = Bc * Qn;          // 8192
    const float scaling = 0.17677669529663687f;  // 1/sqrt(32)

    // 1) projections (tensor cores, bf16x3)
    {
        dim3 grid(M / 128, INNER / 64);
        gemm_tc<<<grid, 256>>>(query, Wq, nullptr, qs,  M, INNER, DQ, scaling);
        gemm_tc<<<grid, 256>>>(key,   Wk, nullptr, ksp, M, INNER, DQ, 1.f);
        gemm_tc<<<grid, 256>>>(value, Wv, nullptr, vsp, M, INNER, DQ, 1.f);
    }
    // 2) softmax shift bound: c = ||q|| * max||k||
    {
        qnorm_kernel<<<Bc * Qn * NH / 256, 256>>>(qs, qnp);
        knorm_kernel<<<Bc * NH, 256>>>(ksp, knp);
    }
    // 3) pass A: row sums l;  pass B: weights + PV (tensor cores via mma.sync)
    {
        cudaFuncSetAttribute(fa_kernel<0>, cudaFuncAttributeMaxDynamicSharedMemorySize, SM_BYTES);
        cudaFuncSetAttribute(fa_kernel<1>, cudaFuncAttributeMaxDynamicSharedMemorySize, SM_BYTES);
        dim3 grid(Qn / 128, NH, Bc);
        fa_kernel<0><<<grid, 256, SM_BYTES>>>(qs, ksp, vsp, qnp, knp, lp, out_w, qop);
        fa_kernel<1><<<grid, 256, SM_BYTES>>>(qs, ksp, vsp, qnp, knp, lp, out_w, qop);
    }
    // 4) output projection + bias (tensor cores, bf16x3)
    {
        dim3 grid(M / 128, DQ / 64);
        gemm_tc<<<grid, 256>>>(qop, Wo, bo, out_attn, M, DQ, INNER, 1.f);
    }
}

// round 13
// speedup vs baseline: 1.8236x; 1.0367x over previous
#include <cuda_runtime.h>
#include <cuda_bf16.h>
#include <math.h>
#include <stdint.h>

// Problem constants
#define Bc   2
#define Qn   4096
#define Kn   4096
#define DQ   512
#define NH   8
#define DH   32
#define INNER (NH*DH)   // 256

// ---------------- scratch (no allocs allowed) ----------------
__device__ float g_qs[Bc*Qn*INNER];   // projected, scaled q  [B,Q,256]
__device__ float g_ks[Bc*Kn*INNER];   // projected k          [B,K,256]
__device__ float g_vs[Bc*Kn*INNER];   // projected v          [B,K,256]
__device__ float g_qo[Bc*Qn*INNER];   // attention out (pre Wo) [B,Q,256]
__device__ float g_qn[Bc*NH*Qn];      // ||q_row||  -> shift c
__device__ float g_il[Bc*NH*Qn];      // 1 / row-sum-exp
__device__ float g_knm[Bc*NH];        // max_k ||k_row||

// ================= mma.sync bf16 plumbing (sm_80+, no 'a' features) ========
__device__ __forceinline__ void mma_bf16(float c[4], const uint32_t a[4],
                                         const uint32_t b[2]) {
    asm volatile(
        "mma.sync.aligned.m16n8k16.row.col.f32.bf16.bf16.f32 "
        "{%0,%1,%2,%3}, {%4,%5,%6,%7}, {%8,%9}, {%0,%1,%2,%3};"
        : "+f"(c[0]), "+f"(c[1]), "+f"(c[2]), "+f"(c[3])
        : "r"(a[0]), "r"(a[1]), "r"(a[2]), "r"(a[3]), "r"(b[0]), "r"(b[1]));
}

__device__ __forceinline__ uint32_t bfpack(float x, float y) {
    __nv_bfloat162 t;
    t.x = __float2bfloat16(x);
    t.y = __float2bfloat16(y);
    return *(uint32_t*)&t;
}
__device__ __forceinline__ float bfhi(float x) {
    return __bfloat162float(__float2bfloat16(x));
}

// ---------------- tensor-core GEMM, bf16x3: C = scale*(A@W) (+bias) --------
// A[M,K] row-major, W[K,N] row-major, C[M,N]. Tile 128x128, 256 thr, 8 warps.
#define G_AH 0        // [16 kd-pairs][128 rows] stride 136
#define G_AL 2176
#define G_BH 4352     // [16 kd-pairs][128 cols] stride 136
#define G_BL 6528
#define G_WORDS 8704  // 34816 B static

__global__ void __launch_bounds__(256)
gemm_tc(const float* __restrict__ A, const float* __restrict__ W,
        const float* __restrict__ bias, float* __restrict__ C,
        int M, int N, int K, float scale) {
    __shared__ float sm[G_WORDS];
    uint32_t* ahw = (uint32_t*)(sm + G_AH);
    uint32_t* alw = (uint32_t*)(sm + G_AL);
    uint32_t* bhw = (uint32_t*)(sm + G_BH);
    uint32_t* blw = (uint32_t*)(sm + G_BL);

    const int bm = blockIdx.x * 128, bn = blockIdx.y * 128;
    const int tid = threadIdx.x;
    const int warp = tid >> 5, lane = tid & 31;
    const int g = lane >> 2, qd = lane & 3;
    const int r0 = warp * 16 + g;

    float o[16][4];
#pragma unroll
    for (int nt = 0; nt < 16; nt++)
#pragma unroll
        for (int j = 0; j < 4; j++) o[nt][j] = 0.f;

    for (int k0 = 0; k0 < K; k0 += 32) {
        __syncthreads();
        // stage A chunk: 128 rows x 16 pairs, hi/lo
#pragma unroll
        for (int i = 0; i < 8; i++) {
            int idx = tid + i * 256;
            int wp = idx >> 7, r = idx & 127;
            float2 v = *(const float2*)&A[(size_t)(bm + r) * K + k0 + 2 * wp];
            float h0 = bfhi(v.x), h1 = bfhi(v.y);
            ahw[wp * 136 + r] = bfpack(h0, h1);
            alw[wp * 136 + r] = bfpack(v.x - h0, v.y - h1);
        }
        // stage B chunk: 128 cols x 16 pairs, hi/lo
#pragma unroll
        for (int i = 0; i < 8; i++) {
            int idx = tid + i * 256;
            int wp = idx >> 7, n = idx & 127;
            float x0 = W[(size_t)(k0 + 2 * wp) * N + bn + n];
            float x1 = W[(size_t)(k0 + 2 * wp + 1) * N + bn + n];
            float h0 = bfhi(x0), h1 = bfhi(x1);
            bhw[wp * 136 + n] = bfpack(h0, h1);
            blw[wp * 136 + n] = bfpack(x0 - h0, x1 - h1);
        }
        __syncthreads();

        uint32_t aH[2][4], aL[2][4];
#pragma unroll
        for (int kst = 0; kst < 2; kst++) {
            int ba = (kst * 8 + qd) * 136 + r0;
            aH[kst][0] = ahw[ba];            aH[kst][1] = ahw[ba + 8];
            aH[kst][2] = ahw[ba + 4 * 136];  aH[kst][3] = ahw[ba + 4 * 136 + 8];
            aL[kst][0] = alw[ba];            aL[kst][1] = alw[ba + 8];
            aL[kst][2] = alw[ba + 4 * 136];  aL[kst][3] = alw[ba + 4 * 136 + 8];
        }
#pragma unroll
        for (int nt = 0; nt < 16; nt++) {
#pragma unroll
            for (int kst = 0; kst < 2; kst++) {
                uint32_t bH[2], bL[2];
                int ba = (kst * 8 + qd) * 136 + nt * 8 + g;
                bH[0] = bhw[ba]; bH[1] = bhw[ba + 4 * 136];
                bL[0] = blw[ba]; bL[1] = blw[ba + 4 * 136];
                mma_bf16(o[nt], aH[kst], bH);
                mma_bf16(o[nt], aH[kst], bL);
                mma_bf16(o[nt], aL[kst], bH);
            }
        }
    }

    // epilogue
#pragma unroll
    for (int nt = 0; nt < 16; nt++) {
        int col = bn + nt * 8 + qd * 2;
        float b0 = 0.f, b1 = 0.f;
        if (bias) { b0 = bias[col]; b1 = bias[col + 1]; }
        *(float2*)&C[(size_t)(bm + r0) * N + col] =
            make_float2(o[nt][0] * scale + b0, o[nt][1] * scale + b1);
        *(float2*)&C[(size_t)(bm + r0 + 8) * N + col] =
            make_float2(o[nt][2] * scale + b0, o[nt][3] * scale + b1);
    }
}

// ---------------- norm kernels (softmax shift bound) ----------------
__global__ void qnorm_kernel(const float* __restrict__ q, float* __restrict__ qn) {
    int t = blockIdx.x * 256 + threadIdx.x;
    int h = t & 7, bq = t >> 3;
    int b = bq >> 12, qq = bq & 4095;
    const float* p = q + (size_t)bq * INNER + h * DH;
    float s = 0.f;
#pragma unroll
    for (int i = 0; i < 8; i++) {
        float4 v = *(const float4*)(p + i * 4);
        s += v.x * v.x + v.y * v.y + v.z * v.z + v.w * v.w;
    }
    qn[((b * NH + h) * Qn) + qq] = sqrtf(s);
}

__global__ void knorm_kernel(const float* __restrict__ k, float* __restrict__ knm) {
    int bh = blockIdx.x;
    int b = bh >> 3, h = bh & 7;
    float mx = 0.f;
    for (int row = threadIdx.x; row < Kn; row += 256) {
        const float* p = k + ((size_t)(b * Kn) + row) * INNER + h * DH;
        float s = 0.f;
#pragma unroll
        for (int i = 0; i < 8; i++) {
            float4 v = *(const float4*)(p + i * 4);
            s += v.x * v.x + v.y * v.y + v.z * v.z + v.w * v.w;
        }
        mx = fmaxf(mx, s);
    }
    __shared__ float red[256];
    red[threadIdx.x] = mx;
    __syncthreads();
    for (int s = 128; s; s >>= 1) {
        if (threadIdx.x < s) red[threadIdx.x] = fmaxf(red[threadIdx.x], red[threadIdx.x + s]);
        __syncthreads();
    }
    if (threadIdx.x == 0) knm[bh] = sqrtf(red[0]);
}

// ---------------- single-pass fused attention, mma.sync bf16x3 --------------
// Writes RAW p = exp(s - c) to wout, accumulates l and unnormalized O,
// divides O by l at the end. wnorm_kernel scales the weights afterwards.
// grid = (Qn/128, NH, Bc), 256 threads (8 warps x 16 q-rows), chunk = 128 kk.
#define S_QH 0                    // [16 kd-pairs][128 rows] stride 136
#define S_QL 2176
#define S_KH 4352                 // [16 kd-pairs][128 cols] stride 136
#define S_KL 6528
#define S_VH 8704                 // [64 kk-pairs][32 d]     stride 40
#define S_VL 11264
#define SM_WORDS 13824
#define SM_BYTES (SM_WORDS*4)     // 55296

__global__ void __launch_bounds__(256, 2)
fa_kernel(const float* __restrict__ qs, const float* __restrict__ ks,
          const float* __restrict__ vs, const float* __restrict__ qn,
          const float* __restrict__ knm, float* __restrict__ ilg,
          float* __restrict__ wout, float* __restrict__ qo) {
    extern __shared__ float sm[];
    uint32_t* qhw = (uint32_t*)(sm + S_QH);
    uint32_t* qlw = (uint32_t*)(sm + S_QL);
    uint32_t* khw = (uint32_t*)(sm + S_KH);
    uint32_t* klw = (uint32_t*)(sm + S_KL);
    uint32_t* vhw = (uint32_t*)(sm + S_VH);
    uint32_t* vlw = (uint32_t*)(sm + S_VL);

    const int b = blockIdx.z, h = blockIdx.y, q0 = blockIdx.x * 128;
    const int tid = threadIdx.x;
    const int warp = tid >> 5, lane = tid & 31;
    const int g = lane >> 2, qd = lane & 3;
    const size_t bh = (size_t)(b * NH + h);

    // ---- stage Q tile: hi/lo bf16 pairs, layout [kd-pair][row] ----
#pragma unroll
    for (int i = 0; i < 8; i++) {
        int idx = tid + i * 256;
        int wp = idx >> 7, r = idx & 127;
        float2 v = *(const float2*)&qs[((size_t)(b * Qn) + q0 + r) * INNER + h * DH + 2 * wp];
        float h0 = bfhi(v.x), h1 = bfhi(v.y);
        qhw[wp * 136 + r] = bfpack(h0, h1);
        qlw[wp * 136 + r] = bfpack(v.x - h0, v.y - h1);
    }

    const int r0 = warp * 16 + g;
    float cp0, cp1;
    {
        float km = knm[bh];
        cp0 = qn[bh * Qn + q0 + r0] * km;
        cp1 = qn[bh * Qn + q0 + r0 + 8] * km;
    }
    float l0 = 0.f, l1 = 0.f;

    __syncthreads();

    // ---- Q A-fragments (persist whole kernel) ----
    uint32_t aH[2][4], aL[2][4];
#pragma unroll
    for (int kst = 0; kst < 2; kst++) {
        int ba = (kst * 8 + qd) * 136 + warp * 16 + g;
        aH[kst][0] = qhw[ba];            aH[kst][1] = qhw[ba + 8];
        aH[kst][2] = qhw[ba + 4 * 136];  aH[kst][3] = qhw[ba + 4 * 136 + 8];
        aL[kst][0] = qlw[ba];            aL[kst][1] = qlw[ba + 8];
        aL[kst][2] = qlw[ba + 4 * 136];  aL[kst][3] = qlw[ba + 4 * 136 + 8];
    }

    float o[4][4];
#pragma unroll
    for (int dt = 0; dt < 4; dt++)
#pragma unroll
        for (int j = 0; j < 4; j++) o[dt][j] = 0.f;

    for (int c = 0; c < Kn / 128; c++) {
        const int c0 = c * 128;
        __syncthreads();

        // ---- stage K chunk ----
#pragma unroll
        for (int i = 0; i < 8; i++) {
            int idx = tid + i * 256;
            int wp = idx >> 7, col = idx & 127;
            float2 v = *(const float2*)&ks[((size_t)(b * Kn) + c0 + col) * INNER + h * DH + 2 * wp];
            float h0 = bfhi(v.x), h1 = bfhi(v.y);
            khw[wp * 136 + col] = bfpack(h0, h1);
            klw[wp * 136 + col] = bfpack(v.x - h0, v.y - h1);
        }
        // ---- stage V chunk ----
#pragma unroll
        for (int i = 0; i < 8; i++) {
            int idx = tid + i * 256;
            int kp = idx >> 5, d = idx & 31;
            float x0 = vs[((size_t)(b * Kn) + c0 + 2 * kp) * INNER + h * DH + d];
            float x1 = vs[((size_t)(b * Kn) + c0 + 2 * kp + 1) * INNER + h * DH + d];
            float h0 = bfhi(x0), h1 = bfhi(x1);
            vhw[kp * 40 + d] = bfpack(h0, h1);
            vlw[kp * 40 + d] = bfpack(x0 - h0, x1 - h1);
        }
        __syncthreads();

#pragma unroll 2
        for (int ksb = 0; ksb < 8; ksb++) {
            uint32_t pH[4], pL[4];
#pragma unroll
            for (int t = 0; t < 2; t++) {
                const int nt = ksb * 2 + t;
                float cacc[4] = {0.f, 0.f, 0.f, 0.f};
#pragma unroll
                for (int kst = 0; kst < 2; kst++) {
                    uint32_t bH[2], bL[2];
                    int ba = (kst * 8 + qd) * 136 + nt * 8 + g;
                    bH[0] = khw[ba]; bH[1] = khw[ba + 4 * 136];
                    bL[0] = klw[ba]; bL[1] = klw[ba + 4 * 136];
                    mma_bf16(cacc, aH[kst], bH);
                    mma_bf16(cacc, aH[kst], bL);
                    mma_bf16(cacc, aL[kst], bH);
                }
                float p0 = __expf(cacc[0] - cp0);
                float p1 = __expf(cacc[1] - cp0);
                float p2 = __expf(cacc[2] - cp1);
                float p3 = __expf(cacc[3] - cp1);
                l0 += p0 + p1;
                l1 += p2 + p3;
                // raw weights (normalized later by wnorm_kernel)
                size_t wb = (bh * Qn + q0 + r0) * (size_t)Kn + c0 + nt * 8 + qd * 2;
                *(float2*)&wout[wb] = make_float2(p0, p1);
                *(float2*)&wout[wb + (size_t)8 * Kn] = make_float2(p2, p3);
                // repack P into A-fragments
                float h0 = bfhi(p0), h1 = bfhi(p1);
                float h2 = bfhi(p2), h3 = bfhi(p3);
                pH[2 * t + 0] = bfpack(h0, h1);
                pH[2 * t + 1] = bfpack(h2, h3);
                pL[2 * t + 0] = bfpack(p0 - h0, p1 - h1);
                pL[2 * t + 1] = bfpack(p2 - h2, p3 - h3);
            }
            // ---- PV: O += P * V over this kk-block ----
#pragma unroll
            for (int dt = 0; dt < 4; dt++) {
                uint32_t bH[2], bL[2];
                int ba = (ksb * 8 + qd) * 40 + dt * 8 + g;
                bH[0] = vhw[ba]; bH[1] = vhw[ba + 4 * 40];
                bL[0] = vlw[ba]; bL[1] = vlw[ba + 4 * 40];
                mma_bf16(o[dt], pH, bH);
                mma_bf16(o[dt], pH, bL);
                mma_bf16(o[dt], pL, bH);
            }
        }
    }

    // ---- reduce l over the 4 qd lanes; normalize O; store 1/l ----
    l0 += __shfl_xor_sync(0xffffffffu, l0, 1);
    l0 += __shfl_xor_sync(0xffffffffu, l0, 2);
    l1 += __shfl_xor_sync(0xffffffffu, l1, 1);
    l1 += __shfl_xor_sync(0xffffffffu, l1, 2);
    float il0 = 1.0f / l0, il1 = 1.0f / l1;
    if (qd == 0) {
        ilg[bh * Qn + q0 + r0] = il0;
        ilg[bh * Qn + q0 + r0 + 8] = il1;
    }
    float* op0 = qo + ((size_t)(b * Qn) + q0 + r0) * INNER + h * DH;
    float* op1 = qo + ((size_t)(b * Qn) + q0 + r0 + 8) * INNER + h * DH;
#pragma unroll
    for (int dt = 0; dt < 4; dt++) {
        *(float2*)&op0[dt * 8 + qd * 2] = make_float2(o[dt][0] * il0, o[dt][1] * il0);
        *(float2*)&op1[dt * 8 + qd * 2] = make_float2(o[dt][2] * il1, o[dt][3] * il1);
    }
}

// ---------------- weights normalize: w *= 1/l (pure bandwidth) --------------
__global__ void wnorm_kernel(float* __restrict__ w, const float* __restrict__ invl) {
    long idx4 = (long)blockIdx.x * 256 + threadIdx.x;
    int row = (int)(idx4 >> 10);       // 1024 float4 per K-row of 4096
    float il = __ldg(&invl[row]);
    float4 v = *(float4*)&w[idx4 * 4];
    v.x *= il; v.y *= il; v.z *= il; v.w *= il;
    *(float4*)&w[idx4 * 4] = v;
}

// ---------------- launch ----------------
extern "C" void kernel_launch(void* const* d_in, const int* in_sizes, int n_in,
                              void* d_out, int out_size) {
    const float* query = (const float*)d_in[0];
    const float* key   = (const float*)d_in[1];
    const float* value = (const float*)d_in[2];
    const float* Wq    = (const float*)d_in[3];
    const float* Wk    = (const float*)d_in[4];
    const float* Wv    = (const float*)d_in[5];
    const float* Wo    = (const float*)d_in[6];
    const float* bo    = (const float*)d_in[7];

    float* out_attn = (float*)d_out;                       // [B,Q,512]
    float* out_w    = (float*)d_out + (size_t)Bc*Qn*DQ;    // [B,H,Q,K]

    float *qs, *ksp, *vsp, *qop, *qnp, *ilp, *knp;
    cudaGetSymbolAddress((void**)&qs,  g_qs);
    cudaGetSymbolAddress((void**)&ksp, g_ks);
    cudaGetSymbolAddress((void**)&vsp, g_vs);
    cudaGetSymbolAddress((void**)&qop, g_qo);
    cudaGetSymbolAddress((void**)&qnp, g_qn);
    cudaGetSymbolAddress((void**)&ilp, g_il);
    cudaGetSymbolAddress((void**)&knp, g_knm);

    const int M = Bc * Qn;          // 8192
    const float scaling = 0.17677669529663687f;  // 1/sqrt(32)

    // 1) projections (tensor cores, bf16x3, 128x128 tiles)
    {
        dim3 grid(M / 128, INNER / 128);
        gemm_tc<<<grid, 256>>>(query, Wq, nullptr, qs,  M, INNER, DQ, scaling);
        gemm_tc<<<grid, 256>>>(key,   Wk, nullptr, ksp, M, INNER, DQ, 1.f);
        gemm_tc<<<grid, 256>>>(value, Wv, nullptr, vsp, M, INNER, DQ, 1.f);
    }
    // 2) softmax shift bound: c = ||q|| * max||k||
    {
        qnorm_kernel<<<Bc * Qn * NH / 256, 256>>>(qs, qnp);
        knorm_kernel<<<Bc * NH, 256>>>(ksp, knp);
    }
    // 3) single-pass attention: raw weights + l + unnormalized O
    {
        cudaFuncSetAttribute(fa_kernel, cudaFuncAttributeMaxDynamicSharedMemorySize, SM_BYTES);
        dim3 grid(Qn / 128, NH, Bc);
        fa_kernel<<<grid, 256, SM_BYTES>>>(qs, ksp, vsp, qnp, knp, ilp, out_w, qop);
    }
    // 4) normalize weights in place (pure bandwidth)
    {
        long n4 = (long)Bc * NH * Qn * Kn / 4;   // 67,108,864
        wnorm_kernel<<<(unsigned)(n4 / 256), 256>>>(out_w, ilp);
    }
    // 5) output projection + bias (tensor cores, bf16x3, 128x128 tiles)
    {
        dim3 grid(M / 128, DQ / 128);
        gemm_tc<<<grid, 256>>>(qop, Wo, bo, out_attn, M, DQ, INNER, 1.f);
    }
}

// round 15
// speedup vs baseline: 1.8917x; 1.0373x over previous
#include <cuda_runtime.h>
#include <cuda_bf16.h>
#include <math.h>
#include <stdint.h>

// Problem constants
#define Bc   2
#define Qn   4096
#define Kn   4096
#define DQ   512
#define NH   8
#define DH   32
#define INNER (NH*DH)   // 256

// ---------------- scratch (no allocs allowed) ----------------
__device__ float g_qs[Bc*Qn*INNER];   // projected q * scaling * log2e  [B,Q,256]
__device__ float g_ks[Bc*Kn*INNER];   // projected k          [B,K,256]
__device__ float g_vs[Bc*Kn*INNER];   // projected v          [B,K,256]
__device__ float g_qo[Bc*Qn*INNER];   // attention out (pre Wo) [B,Q,256]
__device__ float g_qn[Bc*NH*Qn];      // ||q_row|| (log2-domain) -> shift c
__device__ float g_knm[Bc*NH];        // max_k ||k_row||

// ================= mma.sync bf16 plumbing (sm_80+, no 'a' features) ========
__device__ __forceinline__ void mma_bf16(float c[4], const uint32_t a[4],
                                         const uint32_t b[2]) {
    asm volatile(
        "mma.sync.aligned.m16n8k16.row.col.f32.bf16.bf16.f32 "
        "{%0,%1,%2,%3}, {%4,%5,%6,%7}, {%8,%9}, {%0,%1,%2,%3};"
        : "+f"(c[0]), "+f"(c[1]), "+f"(c[2]), "+f"(c[3])
        : "r"(a[0]), "r"(a[1]), "r"(a[2]), "r"(a[3]), "r"(b[0]), "r"(b[1]));
}

__device__ __forceinline__ uint32_t bfpack(float x, float y) {
    __nv_bfloat162 t;
    t.x = __float2bfloat16(x);
    t.y = __float2bfloat16(y);
    return *(uint32_t*)&t;
}
__device__ __forceinline__ float bfhi(float x) {
    return __bfloat162float(__float2bfloat16(x));
}
// fast base-2 exp via MUFU.EX2 (single SASS instruction)
__device__ __forceinline__ float ex2(float x) {
    float r;
    asm("ex2.approx.f32 %0, %1;" : "=f"(r) : "f"(x));
    return r;
}

// ---------------- tensor-core GEMM, bf16x3: C = scale*(A@W) (+bias) --------
// A[M,K] row-major, W[K,N] row-major, C[M,N]. Tile 128x128, 256 thr, 8 warps.
#define G_AH 0        // [16 kd-pairs][128 rows] stride 136
#define G_AL 2176
#define G_BH 4352     // [16 kd-pairs][128 cols] stride 136
#define G_BL 6528
#define G_WORDS 8704  // 34816 B static

__global__ void __launch_bounds__(256)
gemm_tc(const float* __restrict__ A, const float* __restrict__ W,
        const float* __restrict__ bias, float* __restrict__ C,
        int M, int N, int K, float scale) {
    __shared__ float sm[G_WORDS];
    uint32_t* ahw = (uint32_t*)(sm + G_AH);
    uint32_t* alw = (uint32_t*)(sm + G_AL);
    uint32_t* bhw = (uint32_t*)(sm + G_BH);
    uint32_t* blw = (uint32_t*)(sm + G_BL);

    const int bm = blockIdx.x * 128, bn = blockIdx.y * 128;
    const int tid = threadIdx.x;
    const int warp = tid >> 5, lane = tid & 31;
    const int g = lane >> 2, qd = lane & 3;
    const int r0 = warp * 16 + g;

    float o[16][4];
#pragma unroll
    for (int nt = 0; nt < 16; nt++)
#pragma unroll
        for (int j = 0; j < 4; j++) o[nt][j] = 0.f;

    for (int k0 = 0; k0 < K; k0 += 32) {
        __syncthreads();
        // stage A chunk: 128 rows x 16 pairs, hi/lo
#pragma unroll
        for (int i = 0; i < 8; i++) {
            int idx = tid + i * 256;
            int wp = idx >> 7, r = idx & 127;
            float2 v = *(const float2*)&A[(size_t)(bm + r) * K + k0 + 2 * wp];
            float h0 = bfhi(v.x), h1 = bfhi(v.y);
            ahw[wp * 136 + r] = bfpack(h0, h1);
            alw[wp * 136 + r] = bfpack(v.x - h0, v.y - h1);
        }
        // stage B chunk: 128 cols x 16 pairs, hi/lo
#pragma unroll
        for (int i = 0; i < 8; i++) {
            int idx = tid + i * 256;
            int wp = idx >> 7, n = idx & 127;
            float x0 = W[(size_t)(k0 + 2 * wp) * N + bn + n];
            float x1 = W[(size_t)(k0 + 2 * wp + 1) * N + bn + n];
            float h0 = bfhi(x0), h1 = bfhi(x1);
            bhw[wp * 136 + n] = bfpack(h0, h1);
            blw[wp * 136 + n] = bfpack(x0 - h0, x1 - h1);
        }
        __syncthreads();

        uint32_t aH[2][4], aL[2][4];
#pragma unroll
        for (int kst = 0; kst < 2; kst++) {
            int ba = (kst * 8 + qd) * 136 + r0;
            aH[kst][0] = ahw[ba];            aH[kst][1] = ahw[ba + 8];
            aH[kst][2] = ahw[ba + 4 * 136];  aH[kst][3] = ahw[ba + 4 * 136 + 8];
            aL[kst][0] = alw[ba];            aL[kst][1] = alw[ba + 8];
            aL[kst][2] = alw[ba + 4 * 136];  aL[kst][3] = alw[ba + 4 * 136 + 8];
        }
#pragma unroll
        for (int nt = 0; nt < 16; nt++) {
#pragma unroll
            for (int kst = 0; kst < 2; kst++) {
                uint32_t bH[2], bL[2];
                int ba = (kst * 8 + qd) * 136 + nt * 8 + g;
                bH[0] = bhw[ba]; bH[1] = bhw[ba + 4 * 136];
                bL[0] = blw[ba]; bL[1] = blw[ba + 4 * 136];
                mma_bf16(o[nt], aH[kst], bH);
                mma_bf16(o[nt], aH[kst], bL);
                mma_bf16(o[nt], aL[kst], bH);
            }
        }
    }

    // epilogue
#pragma unroll
    for (int nt = 0; nt < 16; nt++) {
        int col = bn + nt * 8 + qd * 2;
        float b0 = 0.f, b1 = 0.f;
        if (bias) { b0 = bias[col]; b1 = bias[col + 1]; }
        *(float2*)&C[(size_t)(bm + r0) * N + col] =
            make_float2(o[nt][0] * scale + b0, o[nt][1] * scale + b1);
        *(float2*)&C[(size_t)(bm + r0 + 8) * N + col] =
            make_float2(o[nt][2] * scale + b0, o[nt][3] * scale + b1);
    }
}

// ---------------- norm kernels (softmax shift bound) ----------------
__global__ void qnorm_kernel(const float* __restrict__ q, float* __restrict__ qn) {
    int t = blockIdx.x * 256 + threadIdx.x;
    int h = t & 7, bq = t >> 3;
    int b = bq >> 12, qq = bq & 4095;
    const float* p = q + (size_t)bq * INNER + h * DH;
    float s = 0.f;
#pragma unroll
    for (int i = 0; i < 8; i++) {
        float4 v = *(const float4*)(p + i * 4);
        s += v.x * v.x + v.y * v.y + v.z * v.z + v.w * v.w;
    }
    qn[((b * NH + h) * Qn) + qq] = sqrtf(s);
}

__global__ void knorm_kernel(const float* __restrict__ k, float* __restrict__ knm) {
    int bh = blockIdx.x;
    int b = bh >> 3, h = bh & 7;
    float mx = 0.f;
    for (int row = threadIdx.x; row < Kn; row += 256) {
        const float* p = k + ((size_t)(b * Kn) + row) * INNER + h * DH;
        float s = 0.f;
#pragma unroll
        for (int i = 0; i < 8; i++) {
            float4 v = *(const float4*)(p + i * 4);
            s += v.x * v.x + v.y * v.y + v.z * v.z + v.w * v.w;
        }
        mx = fmaxf(mx, s);
    }
    __shared__ float red[256];
    red[threadIdx.x] = mx;
    __syncthreads();
    for (int s = 128; s; s >>= 1) {
        if (threadIdx.x < s) red[threadIdx.x] = fmaxf(red[threadIdx.x], red[threadIdx.x + s]);
        __syncthreads();
    }
    if (threadIdx.x == 0) knm[bh] = sqrtf(red[0]);
}

// ---------------- single-pass fused attention + in-kernel weight normalize --
// q is pre-scaled by scaling*log2e, so scores are log2-domain: p = ex2(s - c).
// Writes RAW p to wout during the loop, then the CTA re-streams its own 2MB
// tile scaled by 1/l in the epilogue (overlaps with other CTAs' compute).
// grid = (Qn/128, NH, Bc), 256 threads (8 warps x 16 q-rows), chunk = 128 kk.
#define S_QH 0                    // [16 kd-pairs][128 rows] stride 136
#define S_QL 2176
#define S_KH 4352                 // [16 kd-pairs][128 cols] stride 136
#define S_KL 6528
#define S_VH 8704                 // [64 kk-pairs][32 d]     stride 40
#define S_VL 11264
#define S_IL 13824                // 1/l per row [128]
#define SM_WORDS 13952
#define SM_BYTES (SM_WORDS*4)     // 55808

__global__ void __launch_bounds__(256, 2)
fa_kernel(const float* __restrict__ qs, const float* __restrict__ ks,
          const float* __restrict__ vs, const float* __restrict__ qn,
          const float* __restrict__ knm,
          float* __restrict__ wout, float* __restrict__ qo) {
    extern __shared__ float sm[];
    uint32_t* qhw = (uint32_t*)(sm + S_QH);
    uint32_t* qlw = (uint32_t*)(sm + S_QL);
    uint32_t* khw = (uint32_t*)(sm + S_KH);
    uint32_t* klw = (uint32_t*)(sm + S_KL);
    uint32_t* vhw = (uint32_t*)(sm + S_VH);
    uint32_t* vlw = (uint32_t*)(sm + S_VL);
    float*    ilm = sm + S_IL;

    const int b = blockIdx.z, h = blockIdx.y, q0 = blockIdx.x * 128;
    const int tid = threadIdx.x;
    const int warp = tid >> 5, lane = tid & 31;
    const int g = lane >> 2, qd = lane & 3;
    const size_t bh = (size_t)(b * NH + h);

    // ---- stage Q tile: hi/lo bf16 pairs, layout [kd-pair][row] ----
#pragma unroll
    for (int i = 0; i < 8; i++) {
        int idx = tid + i * 256;
        int wp = idx >> 7, r = idx & 127;
        float2 v = *(const float2*)&qs[((size_t)(b * Qn) + q0 + r) * INNER + h * DH + 2 * wp];
        float h0 = bfhi(v.x), h1 = bfhi(v.y);
        qhw[wp * 136 + r] = bfpack(h0, h1);
        qlw[wp * 136 + r] = bfpack(v.x - h0, v.y - h1);
    }

    const int r0 = warp * 16 + g;
    float cp0, cp1;
    {
        float km = knm[bh];
        cp0 = qn[bh * Qn + q0 + r0] * km;
        cp1 = qn[bh * Qn + q0 + r0 + 8] * km;
    }
    float l0 = 0.f, l1 = 0.f;

    __syncthreads();

    // ---- Q A-fragments (persist whole kernel) ----
    uint32_t aH[2][4], aL[2][4];
#pragma unroll
    for (int kst = 0; kst < 2; kst++) {
        int ba = (kst * 8 + qd) * 136 + warp * 16 + g;
        aH[kst][0] = qhw[ba];            aH[kst][1] = qhw[ba + 8];
        aH[kst][2] = qhw[ba + 4 * 136];  aH[kst][3] = qhw[ba + 4 * 136 + 8];
        aL[kst][0] = qlw[ba];            aL[kst][1] = qlw[ba + 8];
        aL[kst][2] = qlw[ba + 4 * 136];  aL[kst][3] = qlw[ba + 4 * 136 + 8];
    }

    float o[4][4];
#pragma unroll
    for (int dt = 0; dt < 4; dt++)
#pragma unroll
        for (int j = 0; j < 4; j++) o[dt][j] = 0.f;

    for (int c = 0; c < Kn / 128; c++) {
        const int c0 = c * 128;
        __syncthreads();

        // ---- stage K chunk ----
#pragma unroll
        for (int i = 0; i < 8; i++) {
            int idx = tid + i * 256;
            int wp = idx >> 7, col = idx & 127;
            float2 v = *(const float2*)&ks[((size_t)(b * Kn) + c0 + col) * INNER + h * DH + 2 * wp];
            float h0 = bfhi(v.x), h1 = bfhi(v.y);
            khw[wp * 136 + col] = bfpack(h0, h1);
            klw[wp * 136 + col] = bfpack(v.x - h0, v.y - h1);
        }
        // ---- stage V chunk ----
#pragma unroll
        for (int i = 0; i < 8; i++) {
            int idx = tid + i * 256;
            int kp = idx >> 5, d = idx & 31;
            float x0 = vs[((size_t)(b * Kn) + c0 + 2 * kp) * INNER + h * DH + d];
            float x1 = vs[((size_t)(b * Kn) + c0 + 2 * kp + 1) * INNER + h * DH + d];
            float h0 = bfhi(x0), h1 = bfhi(x1);
            vhw[kp * 40 + d] = bfpack(h0, h1);
            vlw[kp * 40 + d] = bfpack(x0 - h0, x1 - h1);
        }
        __syncthreads();

#pragma unroll 2
        for (int ksb = 0; ksb < 8; ksb++) {
            uint32_t pH[4], pL[4];
#pragma unroll
            for (int t = 0; t < 2; t++) {
                const int nt = ksb * 2 + t;
                float cacc[4] = {0.f, 0.f, 0.f, 0.f};
#pragma unroll
                for (int kst = 0; kst < 2; kst++) {
                    uint32_t bH[2], bL[2];
                    int ba = (kst * 8 + qd) * 136 + nt * 8 + g;
                    bH[0] = khw[ba]; bH[1] = khw[ba + 4 * 136];
                    bL[0] = klw[ba]; bL[1] = klw[ba + 4 * 136];
                    mma_bf16(cacc, aH[kst], bH);
                    mma_bf16(cacc, aH[kst], bL);
                    mma_bf16(cacc, aL[kst], bH);
                }
                float p0 = ex2(cacc[0] - cp0);
                float p1 = ex2(cacc[1] - cp0);
                float p2 = ex2(cacc[2] - cp1);
                float p3 = ex2(cacc[3] - cp1);
                l0 += p0 + p1;
                l1 += p2 + p3;
                // raw weights (normalized in the fused epilogue below)
                size_t wb = (bh * Qn + q0 + r0) * (size_t)Kn + c0 + nt * 8 + qd * 2;
                *(float2*)&wout[wb] = make_float2(p0, p1);
                *(float2*)&wout[wb + (size_t)8 * Kn] = make_float2(p2, p3);
                // repack P into A-fragments
                float h0 = bfhi(p0), h1 = bfhi(p1);
                float h2 = bfhi(p2), h3 = bfhi(p3);
                pH[2 * t + 0] = bfpack(h0, h1);
                pH[2 * t + 1] = bfpack(h2, h3);
                pL[2 * t + 0] = bfpack(p0 - h0, p1 - h1);
                pL[2 * t + 1] = bfpack(p2 - h2, p3 - h3);
            }
            // ---- PV: O += P * V over this kk-block ----
#pragma unroll
            for (int dt = 0; dt < 4; dt++) {
                uint32_t bH[2], bL[2];
                int ba = (ksb * 8 + qd) * 40 + dt * 8 + g;
                bH[0] = vhw[ba]; bH[1] = vhw[ba + 4 * 40];
                bL[0] = vlw[ba]; bL[1] = vlw[ba + 4 * 40];
                mma_bf16(o[dt], pH, bH);
                mma_bf16(o[dt], pH, bL);
                mma_bf16(o[dt], pL, bH);
            }
        }
    }

    // ---- reduce l over the 4 qd lanes; normalize O; share 1/l ----
    l0 += __shfl_xor_sync(0xffffffffu, l0, 1);
    l0 += __shfl_xor_sync(0xffffffffu, l0, 2);
    l1 += __shfl_xor_sync(0xffffffffu, l1, 1);
    l1 += __shfl_xor_sync(0xffffffffu, l1, 2);
    float il0 = 1.0f / l0, il1 = 1.0f / l1;
    if (qd == 0) {
        ilm[r0] = il0;
        ilm[r0 + 8] = il1;
    }
    float* op0 = qo + ((size_t)(b * Qn) + q0 + r0) * INNER + h * DH;
    float* op1 = qo + ((size_t)(b * Qn) + q0 + r0 + 8) * INNER + h * DH;
#pragma unroll
    for (int dt = 0; dt < 4; dt++) {
        *(float2*)&op0[dt * 8 + qd * 2] = make_float2(o[dt][0] * il0, o[dt][1] * il0);
        *(float2*)&op1[dt * 8 + qd * 2] = make_float2(o[dt][2] * il1, o[dt][3] * il1);
    }
    __syncthreads();   // orders this CTA's weight STGs + ilm before re-read

    // ---- fused normalize of this CTA's contiguous 2MB weights tile ----
    {
        float* wt = wout + (bh * Qn + q0) * (size_t)Kn;
        for (int i = tid; i < 128 * 1024; i += 256) {
            float il = ilm[i >> 10];          // broadcast within warp
            float4 v = *(float4*)&wt[(size_t)i * 4];
            v.x *= il; v.y *= il; v.z *= il; v.w *= il;
            *(float4*)&wt[(size_t)i * 4] = v;
        }
    }
}

// ---------------- launch ----------------
extern "C" void kernel_launch(void* const* d_in, const int* in_sizes, int n_in,
                              void* d_out, int out_size) {
    const float* query = (const float*)d_in[0];
    const float* key   = (const float*)d_in[1];
    const float* value = (const float*)d_in[2];
    const float* Wq    = (const float*)d_in[3];
    const float* Wk    = (const float*)d_in[4];
    const float* Wv    = (const float*)d_in[5];
    const float* Wo    = (const float*)d_in[6];
    const float* bo    = (const float*)d_in[7];

    float* out_attn = (float*)d_out;                       // [B,Q,512]
    float* out_w    = (float*)d_out + (size_t)Bc*Qn*DQ;    // [B,H,Q,K]

    float *qs, *ksp, *vsp, *qop, *qnp, *knp;
    cudaGetSymbolAddress((void**)&qs,  g_qs);
    cudaGetSymbolAddress((void**)&ksp, g_ks);
    cudaGetSymbolAddress((void**)&vsp, g_vs);
    cudaGetSymbolAddress((void**)&qop, g_qo);
    cudaGetSymbolAddress((void**)&qnp, g_qn);
    cudaGetSymbolAddress((void**)&knp, g_knm);

    const int M = Bc * Qn;          // 8192
    // 1/sqrt(32) * log2(e): scores land in log2 domain -> ex2 in fa_kernel
    const float scaling = 0.17677669529663687f * 1.4426950408889634f;

    // 1) projections (tensor cores, bf16x3, 128x128 tiles)
    {
        dim3 grid(M / 128, INNER / 128);
        gemm_tc<<<grid, 256>>>(query, Wq, nullptr, qs,  M, INNER, DQ, scaling);
        gemm_tc<<<grid, 256>>>(key,   Wk, nullptr, ksp, M, INNER, DQ, 1.f);
        gemm_tc<<<grid, 256>>>(value, Wv, nullptr, vsp, M, INNER, DQ, 1.f);
    }
    // 2) softmax shift bound: c = ||q'|| * max||k||  (log2 domain via q scale)
    {
        qnorm_kernel<<<Bc * Qn * NH / 256, 256>>>(qs, qnp);
        knorm_kernel<<<Bc * NH, 256>>>(ksp, knp);
    }
    // 3) single-pass attention: raw weights + l + O, fused in-place normalize
    {
        cudaFuncSetAttribute(fa_kernel, cudaFuncAttributeMaxDynamicSharedMemorySize, SM_BYTES);
        dim3 grid(Qn / 128, NH, Bc);
        fa_kernel<<<grid, 256, SM_BYTES>>>(qs, ksp, vsp, qnp, knp, out_w, qop);
    }
    // 4) output projection + bias (tensor cores, bf16x3, 128x128 tiles)
    {
        dim3 grid(M / 128, DQ / 128);
        gemm_tc<<<grid, 256>>>(qop, Wo, bo, out_attn, M, DQ, INNER, 1.f);
    }
}